// round 6
// baseline (speedup 1.0000x reference)
#include <cuda_runtime.h>
#include <cuda_bf16.h>
#include <cstdint>

// Problem constants
#define BATCH  8
#define SEQ    1024
#define DIM    1024
#define HEADS  16
#define HDIM   64
#define TOKENS (BATCH * SEQ)          // 8192
#define QKVDIM (3 * DIM)              // 3072
#define SCALE  0.03125f               // 1024^-0.5

// ---------------------------------------------------------------------------
// Scratch (device globals: allocation-guard safe)
// ---------------------------------------------------------------------------
__device__ __nv_bfloat16 g_xhi[(size_t)TOKENS * DIM];
__device__ __nv_bfloat16 g_xlo[(size_t)TOKENS * DIM];
__device__ __nv_bfloat16 g_w1hi[(size_t)QKVDIM * DIM];      // w_qkv^T [3072][1024]
__device__ __nv_bfloat16 g_w1lo[(size_t)QKVDIM * DIM];
__device__ __nv_bfloat16 g_w2hi[(size_t)DIM * DIM];         // w_out^T [1024][1024]
__device__ __nv_bfloat16 g_w2lo[(size_t)DIM * DIM];
__device__ __nv_bfloat16 g_qkvhi[(size_t)TOKENS * QKVDIM];  // qkv hi [8192][3072]
__device__ __nv_bfloat16 g_qkvlo[(size_t)TOKENS * QKVDIM];
__device__ __nv_bfloat16 g_ahi[(size_t)TOKENS * DIM];
__device__ __nv_bfloat16 g_alo[(size_t)TOKENS * DIM];

// ---------------------------------------------------------------------------
// Helpers
// ---------------------------------------------------------------------------
__device__ __forceinline__ uint32_t smem_u32(const void* p) {
    uint32_t a;
    asm("{ .reg .u64 t; cvta.to.shared.u64 t, %1; cvt.u32.u64 %0, t; }" : "=r"(a) : "l"(p));
    return a;
}

__device__ __forceinline__ void cp_async16(uint32_t dst, const void* src) {
    asm volatile("cp.async.cg.shared.global [%0], [%1], 16;\n" :: "r"(dst), "l"(src));
}
#define CP_COMMIT() asm volatile("cp.async.commit_group;\n" ::: "memory")
#define CP_WAIT2()  asm volatile("cp.async.wait_group 2;\n" ::: "memory")
#define CP_WAIT1()  asm volatile("cp.async.wait_group 1;\n" ::: "memory")
#define CP_WAIT0()  asm volatile("cp.async.wait_group 0;\n" ::: "memory")

__device__ __forceinline__ void ldsm_x4(uint32_t* r, uint32_t addr) {
    asm volatile("ldmatrix.sync.aligned.m8n8.x4.shared.b16 {%0,%1,%2,%3}, [%4];"
                 : "=r"(r[0]), "=r"(r[1]), "=r"(r[2]), "=r"(r[3]) : "r"(addr));
}

__device__ __forceinline__ void ldsm_x4_t(uint32_t* r, uint32_t addr) {
    asm volatile("ldmatrix.sync.aligned.m8n8.x4.trans.shared.b16 {%0,%1,%2,%3}, [%4];"
                 : "=r"(r[0]), "=r"(r[1]), "=r"(r[2]), "=r"(r[3]) : "r"(addr));
}

__device__ __forceinline__ void mma_bf16(float* d, const uint32_t* a, const uint32_t* b) {
    asm volatile("mma.sync.aligned.m16n8k16.row.col.f32.bf16.bf16.f32 "
                 "{%0,%1,%2,%3}, {%4,%5,%6,%7}, {%8,%9}, {%0,%1,%2,%3};"
                 : "+f"(d[0]), "+f"(d[1]), "+f"(d[2]), "+f"(d[3])
                 : "r"(a[0]), "r"(a[1]), "r"(a[2]), "r"(a[3]), "r"(b[0]), "r"(b[1]));
}

// pack two fp32 into bf16x2 (lo -> low half)
__device__ __forceinline__ uint32_t pack_bf16(float lo, float hi) {
    uint32_t d;
    asm("cvt.rn.bf16x2.f32 %0, %1, %2;" : "=r"(d) : "f"(hi), "f"(lo));
    return d;
}
// residual pair after bf16 truncation of (lo, hi) packed in hp
__device__ __forceinline__ uint32_t resid_bf16(uint32_t hp, float lo, float hi) {
    float h0 = __bfloat162float(__ushort_as_bfloat16((unsigned short)(hp & 0xffffu)));
    float h1 = __bfloat162float(__ushort_as_bfloat16((unsigned short)(hp >> 16)));
    return pack_bf16(lo - h0, hi - h1);
}

// ---------------------------------------------------------------------------
// Split-bf16 HMMA GEMM: C = (Ahi+Alo)[M,K] @ (Whi+Wlo)[N,K]^T
// OUT==0: write fp32 C (+bias).  OUT==1: write bf16 hi/lo pair (Chi, Clo).
// Block tile 256x128, BK=32, 512 threads = 16 warps (4m x 4n grid of 64x32
// warp tiles). A fragments streamed (not held) to keep regs ~112.
// Double-buffered cp.async, XOR-swizzled smem.
// ---------------------------------------------------------------------------
#define GK     1024
#define BK     32
#define NITER  (GK / BK)               // 32
#define A_TILE (256 * 64)              // 16 KB  [256 rows][32 bf16 = 64B]
#define W_TILE (128 * 64)              // 8 KB
#define STAGEB (2 * A_TILE + 2 * W_TILE)   // 48 KB
#define GEMM_SMEM (2 * STAGEB)             // 96 KB

template<int OUT>
__global__ __launch_bounds__(512, 1) void gemm_mma(
    const __nv_bfloat16* __restrict__ Ahi, const __nv_bfloat16* __restrict__ Alo,
    const __nv_bfloat16* __restrict__ Whi, const __nv_bfloat16* __restrict__ Wlo,
    const float* __restrict__ bias, float* __restrict__ C,
    __nv_bfloat16* __restrict__ Chi, __nv_bfloat16* __restrict__ Clo, int N)
{
    extern __shared__ char sm[];
    const uint32_t sbase = smem_u32(sm);
    const int tid  = threadIdx.x;
    const int lane = tid & 31;
    const int warp = tid >> 5;
    const int wm = warp & 3;              // 4 warp rows (64 m each)
    const int wn = warp >> 2;             // 4 warp cols (32 n each)
    const int m0 = blockIdx.y * 256;
    const int n0 = blockIdx.x * 128;

    float acc[4][4][4];
    #pragma unroll
    for (int i = 0; i < 4; i++)
        #pragma unroll
        for (int j = 0; j < 4; j++)
            #pragma unroll
            for (int q = 0; q < 4; q++) acc[i][j][q] = 0.f;

    auto load_stage = [&](int s, int k0) {
        const uint32_t st = sbase + s * STAGEB;
        // A tiles: 256 rows x 4 chunks = 1024 chunks per tile
        #pragma unroll
        for (int j = 0; j < 2; j++) {
            int id = tid + j * 512;
            int r = id >> 2, c = id & 3;
            uint32_t sw = r * 64 + ((c ^ ((r >> 1) & 3)) << 4);
            size_t go = (size_t)(m0 + r) * GK + k0;
            cp_async16(st + sw,          (const char*)(Ahi + go) + c * 16);
            cp_async16(st + A_TILE + sw, (const char*)(Alo + go) + c * 16);
        }
        // W tiles: 128 rows x 4 chunks = 512 chunks per tile
        {
            int r = tid >> 2, c = tid & 3;
            uint32_t sw = r * 64 + ((c ^ ((r >> 1) & 3)) << 4);
            size_t go = (size_t)(n0 + r) * GK + k0;
            cp_async16(st + 2 * A_TILE + sw,          (const char*)(Whi + go) + c * 16);
            cp_async16(st + 2 * A_TILE + W_TILE + sw, (const char*)(Wlo + go) + c * 16);
        }
        CP_COMMIT();
    };

    load_stage(0, 0);
    load_stage(1, BK);

    const int sub = lane >> 3, rin = lane & 7;
    const int a_row_off = (sub & 1) * 8 + rin;
    const int a_chunk   = sub >> 1;
    const int b_row_off = (sub >> 1) * 8 + rin;
    const int b_chunk   = sub & 1;

    for (int it = 0; it < NITER; it++) {
        const int s = it & 1;
        if (it == NITER - 1) { CP_WAIT0(); } else { CP_WAIT1(); }
        __syncthreads();

        const uint32_t st = sbase + s * STAGEB;
        const uint32_t aH = st, aL = st + A_TILE;
        const uint32_t wH = st + 2 * A_TILE, wL = st + 2 * A_TILE + W_TILE;

        #pragma unroll
        for (int ks = 0; ks < 2; ks++) {
            // B fragments (held: 16 regs)
            uint32_t Bh[4][2], Bl[4][2];
            #pragma unroll
            for (int p = 0; p < 2; p++) {
                int row = wn * 32 + p * 16 + b_row_off;
                int c = ks * 2 + b_chunk;
                uint32_t off = row * 64 + ((c ^ ((row >> 1) & 3)) << 4);
                uint32_t t0[4], t1[4];
                ldsm_x4(t0, wH + off);
                ldsm_x4(t1, wL + off);
                Bh[p*2  ][0] = t0[0]; Bh[p*2  ][1] = t0[1];
                Bh[p*2+1][0] = t0[2]; Bh[p*2+1][1] = t0[3];
                Bl[p*2  ][0] = t1[0]; Bl[p*2  ][1] = t1[1];
                Bl[p*2+1][0] = t1[2]; Bl[p*2+1][1] = t1[3];
            }
            // A fragments streamed per mi (8 live regs)
            #pragma unroll
            for (int mi = 0; mi < 4; mi++) {
                int row = wm * 64 + mi * 16 + a_row_off;
                int c = ks * 2 + a_chunk;
                uint32_t off = row * 64 + ((c ^ ((row >> 1) & 3)) << 4);
                uint32_t Ah4[4], Al4[4];
                ldsm_x4(Ah4, aH + off);
                ldsm_x4(Al4, aL + off);
                #pragma unroll
                for (int ni = 0; ni < 4; ni++) {
                    mma_bf16(acc[mi][ni], Ah4, Bh[ni]);
                    mma_bf16(acc[mi][ni], Ah4, Bl[ni]);
                    mma_bf16(acc[mi][ni], Al4, Bh[ni]);
                }
            }
        }
        __syncthreads();
        if (it + 2 < NITER) load_stage(s, (it + 2) * BK);
    }

    const int g = lane >> 2, c2 = (lane & 3) * 2;
    #pragma unroll
    for (int mi = 0; mi < 4; mi++) {
        int row = m0 + wm * 64 + mi * 16 + g;
        #pragma unroll
        for (int ni = 0; ni < 4; ni++) {
            int col = n0 + wn * 32 + ni * 8 + c2;
            if (OUT == 0) {
                float b0 = 0.f, b1 = 0.f;
                if (bias) { b0 = bias[col]; b1 = bias[col + 1]; }
                float2 v0 = make_float2(acc[mi][ni][0] + b0, acc[mi][ni][1] + b1);
                float2 v1 = make_float2(acc[mi][ni][2] + b0, acc[mi][ni][3] + b1);
                *(float2*)&C[(size_t)row * N + col] = v0;
                *(float2*)&C[(size_t)(row + 8) * N + col] = v1;
            } else {
                uint32_t hp0 = pack_bf16(acc[mi][ni][0], acc[mi][ni][1]);
                uint32_t hp1 = pack_bf16(acc[mi][ni][2], acc[mi][ni][3]);
                uint32_t lp0 = resid_bf16(hp0, acc[mi][ni][0], acc[mi][ni][1]);
                uint32_t lp1 = resid_bf16(hp1, acc[mi][ni][2], acc[mi][ni][3]);
                *(uint32_t*)&Chi[(size_t)row * N + col] = hp0;
                *(uint32_t*)&Chi[(size_t)(row + 8) * N + col] = hp1;
                *(uint32_t*)&Clo[(size_t)row * N + col] = lp0;
                *(uint32_t*)&Clo[(size_t)(row + 8) * N + col] = lp1;
            }
        }
    }
}

// ---------------------------------------------------------------------------
// fp32 -> bf16 hi/lo split (elementwise, float4)
// ---------------------------------------------------------------------------
__global__ __launch_bounds__(256) void split_kernel(
    const float* __restrict__ in, __nv_bfloat16* __restrict__ hi,
    __nv_bfloat16* __restrict__ lo, int n4)
{
    int i = blockIdx.x * blockDim.x + threadIdx.x;
    if (i >= n4) return;
    float4 v = ((const float4*)in)[i];
    __nv_bfloat16 h[4], l[4];
    float f[4] = {v.x, v.y, v.z, v.w};
    #pragma unroll
    for (int j = 0; j < 4; j++) {
        h[j] = __float2bfloat16(f[j]);
        l[j] = __float2bfloat16(f[j] - __bfloat162float(h[j]));
    }
    ((ushort4*)hi)[i] = make_ushort4(__bfloat16_as_ushort(h[0]), __bfloat16_as_ushort(h[1]),
                                     __bfloat16_as_ushort(h[2]), __bfloat16_as_ushort(h[3]));
    ((ushort4*)lo)[i] = make_ushort4(__bfloat16_as_ushort(l[0]), __bfloat16_as_ushort(l[1]),
                                     __bfloat16_as_ushort(l[2]), __bfloat16_as_ushort(l[3]));
}

// ---------------------------------------------------------------------------
// fp32 [K][N] -> transposed bf16 hi/lo [N][K]
// ---------------------------------------------------------------------------
__global__ __launch_bounds__(256) void splitT_kernel(
    const float* __restrict__ w, __nv_bfloat16* __restrict__ thi,
    __nv_bfloat16* __restrict__ tlo, int K, int N)
{
    __shared__ float t[32][33];
    const int n0 = blockIdx.x * 32, k0 = blockIdx.y * 32;
    const int tx = threadIdx.x & 31, ty = threadIdx.x >> 5;
    #pragma unroll
    for (int j = ty; j < 32; j += 8)
        t[j][tx] = w[(size_t)(k0 + j) * N + n0 + tx];
    __syncthreads();
    #pragma unroll
    for (int j = ty; j < 32; j += 8) {
        float v = t[tx][j];
        __nv_bfloat16 h = __float2bfloat16(v);
        __nv_bfloat16 l = __float2bfloat16(v - __bfloat162float(h));
        thi[(size_t)(n0 + j) * K + k0 + tx] = h;
        tlo[(size_t)(n0 + j) * K + k0 + tx] = l;
    }
}

// ---------------------------------------------------------------------------
// HMMA flash attention, split-bf16 (unchanged — known-good).
// ---------------------------------------------------------------------------
#define AT_Q    0
#define AT_QL   16384
#define AT_ST   32768
#define AT_STB  32768
#define AT_KH   0
#define AT_KL   8192
#define AT_VH   16384
#define AT_VL   24576
#define AT_SMEM (AT_ST + 2 * AT_STB)   // 98304

__global__ __launch_bounds__(256, 1) void attn_mma(
    const __nv_bfloat16* __restrict__ qh, const __nv_bfloat16* __restrict__ ql,
    __nv_bfloat16* __restrict__ ohi, __nv_bfloat16* __restrict__ olo)
{
    extern __shared__ char sm[];
    const uint32_t sb = smem_u32(sm);
    const int tid  = threadIdx.x;
    const int lane = tid & 31;
    const int warp = tid >> 5;
    const int sub = lane >> 3, rin = lane & 7;
    const int g = lane >> 2, t = lane & 3;

    const int qt = blockIdx.x, head = blockIdx.y, batch = blockIdx.z;
    const size_t tok0 = (size_t)batch * SEQ;
    const size_t qbase = (tok0 + qt * 128) * QKVDIM + head * HDIM;

    #pragma unroll
    for (int j = 0; j < 4; j++) {
        int id = tid + j * 256;
        int r = id >> 3, c = id & 7;
        uint32_t sw = r * 128 + ((c ^ (r & 7)) << 4);
        size_t go = (size_t)r * QKVDIM * 2 + c * 16;
        cp_async16(sb + AT_Q  + sw, (const char*)(qh + qbase) + go);
        cp_async16(sb + AT_QL + sw, (const char*)(ql + qbase) + go);
    }
    CP_COMMIT();

    auto load_kv = [&](int s, int jt) {
        size_t kb = (tok0 + jt * 64) * QKVDIM + DIM + head * HDIM;
        size_t vb = kb + DIM;
        uint32_t st = sb + AT_ST + s * AT_STB;
        #pragma unroll
        for (int j = 0; j < 2; j++) {
            int id = tid + j * 256;
            int r = id >> 3, c = id & 7;
            uint32_t sw = r * 128 + ((c ^ (r & 7)) << 4);
            size_t go = (size_t)r * QKVDIM * 2 + c * 16;
            cp_async16(st + AT_KH + sw, (const char*)(qh + kb) + go);
            cp_async16(st + AT_KL + sw, (const char*)(ql + kb) + go);
            cp_async16(st + AT_VH + sw, (const char*)(qh + vb) + go);
            cp_async16(st + AT_VL + sw, (const char*)(ql + vb) + go);
        }
        CP_COMMIT();
    };

    load_kv(0, 0);
    load_kv(1, 1);

    CP_WAIT2();
    __syncthreads();
    uint32_t Qh[4][4], Ql[4][4];
    {
        int row = warp * 16 + (sub & 1) * 8 + rin;
        #pragma unroll
        for (int s4 = 0; s4 < 4; s4++) {
            int ch = 2 * s4 + (sub >> 1);
            uint32_t off = row * 128 + ((ch ^ (row & 7)) << 4);
            ldsm_x4(Qh[s4], sb + AT_Q  + off);
            ldsm_x4(Ql[s4], sb + AT_QL + off);
        }
    }

    float m0 = -1e30f, m1 = -1e30f, l0 = 0.f, l1 = 0.f;
    float O[8][4];
    #pragma unroll
    for (int b = 0; b < 8; b++)
        #pragma unroll
        for (int q = 0; q < 4; q++) O[b][q] = 0.f;

    for (int jt = 0; jt < SEQ / 64; jt++) {
        const int s = jt & 1;
        if (jt == SEQ / 64 - 1) { CP_WAIT0(); } else { CP_WAIT1(); }
        __syncthreads();
        const uint32_t stb = sb + AT_ST + s * AT_STB;

        float S[8][4];
        #pragma unroll
        for (int b = 0; b < 8; b++)
            #pragma unroll
            for (int q = 0; q < 4; q++) S[b][q] = 0.f;

        #pragma unroll
        for (int s4 = 0; s4 < 4; s4++) {
            int bch = 2 * s4 + (sub & 1);
            #pragma unroll
            for (int jp = 0; jp < 4; jp++) {
                int row = jp * 16 + (sub >> 1) * 8 + rin;
                uint32_t off = row * 128 + ((bch ^ (row & 7)) << 4);
                uint32_t kh[4], kl[4];
                ldsm_x4(kh, stb + AT_KH + off);
                ldsm_x4(kl, stb + AT_KL + off);
                mma_bf16(S[2*jp],   Qh[s4], kh);
                mma_bf16(S[2*jp],   Qh[s4], kl);
                mma_bf16(S[2*jp],   Ql[s4], kh);
                mma_bf16(S[2*jp+1], Qh[s4], kh + 2);
                mma_bf16(S[2*jp+1], Qh[s4], kl + 2);
                mma_bf16(S[2*jp+1], Ql[s4], kh + 2);
            }
        }

        float mx0 = -1e30f, mx1 = -1e30f;
        #pragma unroll
        for (int b = 0; b < 8; b++) {
            #pragma unroll
            for (int q = 0; q < 4; q++) S[b][q] *= SCALE;
            mx0 = fmaxf(mx0, fmaxf(S[b][0], S[b][1]));
            mx1 = fmaxf(mx1, fmaxf(S[b][2], S[b][3]));
        }
        #pragma unroll
        for (int off = 1; off < 4; off <<= 1) {
            mx0 = fmaxf(mx0, __shfl_xor_sync(0xffffffffu, mx0, off));
            mx1 = fmaxf(mx1, __shfl_xor_sync(0xffffffffu, mx1, off));
        }
        float mn0 = fmaxf(m0, mx0), mn1 = fmaxf(m1, mx1);
        float al0 = __expf(m0 - mn0), al1 = __expf(m1 - mn1);
        m0 = mn0; m1 = mn1;

        float rs0 = 0.f, rs1 = 0.f;
        #pragma unroll
        for (int b = 0; b < 8; b++) {
            S[b][0] = __expf(S[b][0] - mn0); rs0 += S[b][0];
            S[b][1] = __expf(S[b][1] - mn0); rs0 += S[b][1];
            S[b][2] = __expf(S[b][2] - mn1); rs1 += S[b][2];
            S[b][3] = __expf(S[b][3] - mn1); rs1 += S[b][3];
        }
        #pragma unroll
        for (int off = 1; off < 4; off <<= 1) {
            rs0 += __shfl_xor_sync(0xffffffffu, rs0, off);
            rs1 += __shfl_xor_sync(0xffffffffu, rs1, off);
        }
        l0 = l0 * al0 + rs0;
        l1 = l1 * al1 + rs1;
        #pragma unroll
        for (int b = 0; b < 8; b++) {
            O[b][0] *= al0; O[b][1] *= al0;
            O[b][2] *= al1; O[b][3] *= al1;
        }

        #pragma unroll
        for (int a = 0; a < 4; a++) {
            uint32_t Ph[4], Pl[4];
            Ph[0] = pack_bf16(S[2*a][0],   S[2*a][1]);
            Ph[1] = pack_bf16(S[2*a][2],   S[2*a][3]);
            Ph[2] = pack_bf16(S[2*a+1][0], S[2*a+1][1]);
            Ph[3] = pack_bf16(S[2*a+1][2], S[2*a+1][3]);
            Pl[0] = resid_bf16(Ph[0], S[2*a][0],   S[2*a][1]);
            Pl[1] = resid_bf16(Ph[1], S[2*a][2],   S[2*a][3]);
            Pl[2] = resid_bf16(Ph[2], S[2*a+1][0], S[2*a+1][1]);
            Pl[3] = resid_bf16(Ph[3], S[2*a+1][2], S[2*a+1][3]);

            int vrow = a * 16 + (sub & 1) * 8 + rin;
            #pragma unroll
            for (int bp = 0; bp < 4; bp++) {
                int ch = 2 * bp + (sub >> 1);
                uint32_t off = vrow * 128 + ((ch ^ (vrow & 7)) << 4);
                uint32_t vh[4], vl[4];
                ldsm_x4_t(vh, stb + AT_VH + off);
                ldsm_x4_t(vl, stb + AT_VL + off);
                mma_bf16(O[2*bp],   Ph, vh);
                mma_bf16(O[2*bp],   Ph, vl);
                mma_bf16(O[2*bp],   Pl, vh);
                mma_bf16(O[2*bp+1], Ph, vh + 2);
                mma_bf16(O[2*bp+1], Ph, vl + 2);
                mma_bf16(O[2*bp+1], Pl, vh + 2);
            }
        }
        __syncthreads();
        if (jt + 2 < SEQ / 64) load_kv(s, jt + 2);
    }

    float inv0 = 1.f / l0, inv1 = 1.f / l1;
    size_t t0 = tok0 + qt * 128 + warp * 16 + g;
    size_t t1 = t0 + 8;
    #pragma unroll
    for (int b = 0; b < 8; b++) {
        int col = head * HDIM + b * 8 + 2 * t;
        float o00 = O[b][0] * inv0, o01 = O[b][1] * inv0;
        float o10 = O[b][2] * inv1, o11 = O[b][3] * inv1;
        uint32_t hp0 = pack_bf16(o00, o01);
        uint32_t hp1 = pack_bf16(o10, o11);
        *(uint32_t*)&ohi[t0 * DIM + col] = hp0;
        *(uint32_t*)&ohi[t1 * DIM + col] = hp1;
        *(uint32_t*)&olo[t0 * DIM + col] = resid_bf16(hp0, o00, o01);
        *(uint32_t*)&olo[t1 * DIM + col] = resid_bf16(hp1, o10, o11);
    }
}

// ----------------------------------------------------------------------------
// Launch
// ----------------------------------------------------------------------------
extern "C" void kernel_launch(void* const* d_in, const int* in_sizes, int n_in,
                              void* d_out, int out_size)
{
    const float* x     = (const float*)d_in[0];
    const float* w_qkv = (const float*)d_in[1];
    const float* w_out = (const float*)d_in[2];
    const float* b_out = (const float*)d_in[3];
    float* out = (float*)d_out;

    void *p_xhi, *p_xlo, *p_w1hi, *p_w1lo, *p_w2hi, *p_w2lo,
         *p_qh, *p_ql, *p_ahi, *p_alo;
    cudaGetSymbolAddress(&p_xhi, g_xhi);
    cudaGetSymbolAddress(&p_xlo, g_xlo);
    cudaGetSymbolAddress(&p_w1hi, g_w1hi);
    cudaGetSymbolAddress(&p_w1lo, g_w1lo);
    cudaGetSymbolAddress(&p_w2hi, g_w2hi);
    cudaGetSymbolAddress(&p_w2lo, g_w2lo);
    cudaGetSymbolAddress(&p_qh, g_qkvhi);
    cudaGetSymbolAddress(&p_ql, g_qkvlo);
    cudaGetSymbolAddress(&p_ahi, g_ahi);
    cudaGetSymbolAddress(&p_alo, g_alo);

    cudaFuncSetAttribute(gemm_mma<0>, cudaFuncAttributeMaxDynamicSharedMemorySize, GEMM_SMEM);
    cudaFuncSetAttribute(gemm_mma<1>, cudaFuncAttributeMaxDynamicSharedMemorySize, GEMM_SMEM);
    cudaFuncSetAttribute(attn_mma,    cudaFuncAttributeMaxDynamicSharedMemorySize, AT_SMEM);

    // 0) split inputs / weights into bf16 hi+lo
    split_kernel<<<(TOKENS * DIM / 4 + 255) / 256, 256>>>(
        x, (__nv_bfloat16*)p_xhi, (__nv_bfloat16*)p_xlo, TOKENS * DIM / 4);
    splitT_kernel<<<dim3(QKVDIM / 32, DIM / 32), 256>>>(
        w_qkv, (__nv_bfloat16*)p_w1hi, (__nv_bfloat16*)p_w1lo, DIM, QKVDIM);
    splitT_kernel<<<dim3(DIM / 32, DIM / 32), 256>>>(
        w_out, (__nv_bfloat16*)p_w2hi, (__nv_bfloat16*)p_w2lo, DIM, DIM);

    // 1) qkv = x @ w_qkv -> bf16 hi/lo directly     [8192, 3072]
    gemm_mma<1><<<dim3(QKVDIM / 128, TOKENS / 256), 512, GEMM_SMEM>>>(
        (const __nv_bfloat16*)p_xhi, (const __nv_bfloat16*)p_xlo,
        (const __nv_bfloat16*)p_w1hi, (const __nv_bfloat16*)p_w1lo,
        nullptr, nullptr,
        (__nv_bfloat16*)p_qh, (__nv_bfloat16*)p_ql, QKVDIM);

    // 2) attention -> bf16 hi/lo directly            [8192, 1024]
    attn_mma<<<dim3(SEQ / 128, HEADS, BATCH), 256, AT_SMEM>>>(
        (const __nv_bfloat16*)p_qh, (const __nv_bfloat16*)p_ql,
        (__nv_bfloat16*)p_ahi, (__nv_bfloat16*)p_alo);

    // 3) out = attn @ w_out + b                      [8192, 1024]
    gemm_mma<0><<<dim3(DIM / 128, TOKENS / 256), 512, GEMM_SMEM>>>(
        (const __nv_bfloat16*)p_ahi, (const __nv_bfloat16*)p_alo,
        (const __nv_bfloat16*)p_w2hi, (const __nv_bfloat16*)p_w2lo,
        b_out, out, nullptr, nullptr, DIM);
}

// round 7
// speedup vs baseline: 1.1684x; 1.1684x over previous
#include <cuda_runtime.h>
#include <cuda_bf16.h>
#include <cstdint>

// Problem constants
#define BATCH  8
#define SEQ    1024
#define DIM    1024
#define HEADS  16
#define HDIM   64
#define TOKENS (BATCH * SEQ)          // 8192
#define QKVDIM (3 * DIM)              // 3072
#define SCALE  0.03125f               // 1024^-0.5

// ---------------------------------------------------------------------------
// Scratch (device globals: allocation-guard safe)
// ---------------------------------------------------------------------------
__device__ __nv_bfloat16 g_xhi[(size_t)TOKENS * DIM];
__device__ __nv_bfloat16 g_xlo[(size_t)TOKENS * DIM];
__device__ __nv_bfloat16 g_w1hi[(size_t)QKVDIM * DIM];      // w_qkv^T [3072][1024]
__device__ __nv_bfloat16 g_w1lo[(size_t)QKVDIM * DIM];
__device__ __nv_bfloat16 g_w2hi[(size_t)DIM * DIM];         // w_out^T [1024][1024]
__device__ __nv_bfloat16 g_w2lo[(size_t)DIM * DIM];
__device__ __nv_bfloat16 g_qkvhi[(size_t)TOKENS * QKVDIM];  // qkv hi [8192][3072]
__device__ __nv_bfloat16 g_qkvlo[(size_t)TOKENS * QKVDIM];
__device__ __nv_bfloat16 g_ahi[(size_t)TOKENS * DIM];
__device__ __nv_bfloat16 g_alo[(size_t)TOKENS * DIM];

// ---------------------------------------------------------------------------
// Helpers
// ---------------------------------------------------------------------------
__device__ __forceinline__ uint32_t smem_u32(const void* p) {
    uint32_t a;
    asm("{ .reg .u64 t; cvta.to.shared.u64 t, %1; cvt.u32.u64 %0, t; }" : "=r"(a) : "l"(p));
    return a;
}

__device__ __forceinline__ void cp_async16(uint32_t dst, const void* src) {
    asm volatile("cp.async.cg.shared.global [%0], [%1], 16;\n" :: "r"(dst), "l"(src));
}
#define CP_COMMIT() asm volatile("cp.async.commit_group;\n" ::: "memory")
#define CP_WAIT2()  asm volatile("cp.async.wait_group 2;\n" ::: "memory")
#define CP_WAIT1()  asm volatile("cp.async.wait_group 1;\n" ::: "memory")
#define CP_WAIT0()  asm volatile("cp.async.wait_group 0;\n" ::: "memory")

__device__ __forceinline__ void ldsm_x4(uint32_t* r, uint32_t addr) {
    asm volatile("ldmatrix.sync.aligned.m8n8.x4.shared.b16 {%0,%1,%2,%3}, [%4];"
                 : "=r"(r[0]), "=r"(r[1]), "=r"(r[2]), "=r"(r[3]) : "r"(addr));
}

__device__ __forceinline__ void ldsm_x4_t(uint32_t* r, uint32_t addr) {
    asm volatile("ldmatrix.sync.aligned.m8n8.x4.trans.shared.b16 {%0,%1,%2,%3}, [%4];"
                 : "=r"(r[0]), "=r"(r[1]), "=r"(r[2]), "=r"(r[3]) : "r"(addr));
}

__device__ __forceinline__ void mma_bf16(float* d, const uint32_t* a, const uint32_t* b) {
    asm volatile("mma.sync.aligned.m16n8k16.row.col.f32.bf16.bf16.f32 "
                 "{%0,%1,%2,%3}, {%4,%5,%6,%7}, {%8,%9}, {%0,%1,%2,%3};"
                 : "+f"(d[0]), "+f"(d[1]), "+f"(d[2]), "+f"(d[3])
                 : "r"(a[0]), "r"(a[1]), "r"(a[2]), "r"(a[3]), "r"(b[0]), "r"(b[1]));
}

// pack two fp32 into bf16x2 (lo -> low half)
__device__ __forceinline__ uint32_t pack_bf16(float lo, float hi) {
    uint32_t d;
    asm("cvt.rn.bf16x2.f32 %0, %1, %2;" : "=r"(d) : "f"(hi), "f"(lo));
    return d;
}
// residual pair after bf16 truncation of (lo, hi) packed in hp
__device__ __forceinline__ uint32_t resid_bf16(uint32_t hp, float lo, float hi) {
    float h0 = __bfloat162float(__ushort_as_bfloat16((unsigned short)(hp & 0xffffu)));
    float h1 = __bfloat162float(__ushort_as_bfloat16((unsigned short)(hp >> 16)));
    return pack_bf16(lo - h0, hi - h1);
}

// ---------------------------------------------------------------------------
// Split-bf16 HMMA GEMM: C = (Ahi+Alo)[M,K] @ (Whi+Wlo)[N,K]^T
// OUT==0: write fp32 C (+bias).  OUT==1: write bf16 hi/lo pair (Chi, Clo).
// Block 128x128, BK=32, 256 threads (8 warps, 2x4 grid of 64x32 warp tiles).
// 3-stage cp.async pipeline (one barrier per BK iter), XOR-swizzled smem,
// pass-major mma ordering (16 independent accumulators per pass).
// ---------------------------------------------------------------------------
#define GK     1024
#define BK     32
#define NITER  (GK / BK)               // 32
#define TILEB  (128 * 64)              // [128 rows][32 bf16 = 64B]
#define STAGEB (4 * TILEB)             // 32 KB (Ahi, Alo, Whi, Wlo)
#define NSTAGE 3
#define GEMM_SMEM (NSTAGE * STAGEB)    // 96 KB

template<int OUT>
__global__ __launch_bounds__(256, 2) void gemm_mma(
    const __nv_bfloat16* __restrict__ Ahi, const __nv_bfloat16* __restrict__ Alo,
    const __nv_bfloat16* __restrict__ Whi, const __nv_bfloat16* __restrict__ Wlo,
    const float* __restrict__ bias, float* __restrict__ C,
    __nv_bfloat16* __restrict__ Chi, __nv_bfloat16* __restrict__ Clo, int N)
{
    extern __shared__ char sm[];
    const uint32_t sbase = smem_u32(sm);
    const int tid  = threadIdx.x;
    const int lane = tid & 31;
    const int warp = tid >> 5;
    const int wm = warp & 1;
    const int wn = warp >> 1;
    const int m0 = blockIdx.y * 128;
    const int n0 = blockIdx.x * 128;

    float acc[4][4][4];
    #pragma unroll
    for (int i = 0; i < 4; i++)
        #pragma unroll
        for (int j = 0; j < 4; j++)
            #pragma unroll
            for (int q = 0; q < 4; q++) acc[i][j][q] = 0.f;

    const __nv_bfloat16* gs[4] = {Ahi, Alo, Whi, Wlo};
    const int r0s[4] = {m0, m0, n0, n0};

    auto soff = [&](int s, int t) -> uint32_t { return sbase + s * STAGEB + t * TILEB; };

    auto load_stage = [&](int s, int k0) {
        #pragma unroll
        for (int t = 0; t < 4; t++) {
            const char* gp = (const char*)(gs[t] + (size_t)r0s[t] * GK + k0);
            #pragma unroll
            for (int j = 0; j < 2; j++) {
                int id = tid + j * 256;
                int r = id >> 2, c = id & 3;
                uint32_t sw = r * 64 + ((c ^ ((r >> 1) & 3)) << 4);
                cp_async16(soff(s, t) + sw, gp + (size_t)r * (GK * 2) + c * 16);
            }
        }
        CP_COMMIT();
    };

    load_stage(0, 0);
    load_stage(1, BK);

    const int sub = lane >> 3, rin = lane & 7;
    const int a_row_off = (sub & 1) * 8 + rin;
    const int a_chunk   = sub >> 1;
    const int b_row_off = (sub >> 1) * 8 + rin;
    const int b_chunk   = sub & 1;

    for (int it = 0; it < NITER; it++) {
        const int s = it % NSTAGE;
        if (it == NITER - 1) { CP_WAIT0(); } else { CP_WAIT1(); }
        __syncthreads();   // all warps see stage s; all done reading stage (it-1)%3

        const uint32_t aH = soff(s, 0), aL = soff(s, 1);
        const uint32_t wH = soff(s, 2), wL = soff(s, 3);

        #pragma unroll
        for (int ks = 0; ks < 2; ks++) {
            uint32_t Ah[4][4], Al[4][4], Bh[4][2], Bl[4][2];

            #pragma unroll
            for (int mi = 0; mi < 4; mi++) {
                int row = wm * 64 + mi * 16 + a_row_off;
                int c = ks * 2 + a_chunk;
                uint32_t off = row * 64 + ((c ^ ((row >> 1) & 3)) << 4);
                ldsm_x4(Ah[mi], aH + off);
                ldsm_x4(Al[mi], aL + off);
            }
            #pragma unroll
            for (int p = 0; p < 2; p++) {
                int row = wn * 32 + p * 16 + b_row_off;
                int c = ks * 2 + b_chunk;
                uint32_t off = row * 64 + ((c ^ ((row >> 1) & 3)) << 4);
                uint32_t t0[4], t1[4];
                ldsm_x4(t0, wH + off);
                ldsm_x4(t1, wL + off);
                Bh[p*2  ][0] = t0[0]; Bh[p*2  ][1] = t0[1];
                Bh[p*2+1][0] = t0[2]; Bh[p*2+1][1] = t0[3];
                Bl[p*2  ][0] = t1[0]; Bl[p*2  ][1] = t1[1];
                Bl[p*2+1][0] = t1[2]; Bl[p*2+1][1] = t1[3];
            }

            // pass-major: 16 independent accumulators per pass
            #pragma unroll
            for (int mi = 0; mi < 4; mi++)
                #pragma unroll
                for (int ni = 0; ni < 4; ni++)
                    mma_bf16(acc[mi][ni], Ah[mi], Bh[ni]);   // hi*hi
            #pragma unroll
            for (int mi = 0; mi < 4; mi++)
                #pragma unroll
                for (int ni = 0; ni < 4; ni++)
                    mma_bf16(acc[mi][ni], Ah[mi], Bl[ni]);   // hi*lo
            #pragma unroll
            for (int mi = 0; mi < 4; mi++)
                #pragma unroll
                for (int ni = 0; ni < 4; ni++)
                    mma_bf16(acc[mi][ni], Al[mi], Bh[ni]);   // lo*hi
        }
        // prefetch stage (it+2)%3 == stage (it-1)%3, already drained by the
        // barrier at the top of this iteration -> no second barrier needed
        if (it + 2 < NITER) load_stage((it + 2) % NSTAGE, (it + 2) * BK);
    }

    const int g = lane >> 2, c2 = (lane & 3) * 2;
    #pragma unroll
    for (int mi = 0; mi < 4; mi++) {
        int row = m0 + wm * 64 + mi * 16 + g;
        #pragma unroll
        for (int ni = 0; ni < 4; ni++) {
            int col = n0 + wn * 32 + ni * 8 + c2;
            if (OUT == 0) {
                float b0 = 0.f, b1 = 0.f;
                if (bias) { b0 = bias[col]; b1 = bias[col + 1]; }
                float2 v0 = make_float2(acc[mi][ni][0] + b0, acc[mi][ni][1] + b1);
                float2 v1 = make_float2(acc[mi][ni][2] + b0, acc[mi][ni][3] + b1);
                *(float2*)&C[(size_t)row * N + col] = v0;
                *(float2*)&C[(size_t)(row + 8) * N + col] = v1;
            } else {
                uint32_t hp0 = pack_bf16(acc[mi][ni][0], acc[mi][ni][1]);
                uint32_t hp1 = pack_bf16(acc[mi][ni][2], acc[mi][ni][3]);
                uint32_t lp0 = resid_bf16(hp0, acc[mi][ni][0], acc[mi][ni][1]);
                uint32_t lp1 = resid_bf16(hp1, acc[mi][ni][2], acc[mi][ni][3]);
                *(uint32_t*)&Chi[(size_t)row * N + col] = hp0;
                *(uint32_t*)&Chi[(size_t)(row + 8) * N + col] = hp1;
                *(uint32_t*)&Clo[(size_t)row * N + col] = lp0;
                *(uint32_t*)&Clo[(size_t)(row + 8) * N + col] = lp1;
            }
        }
    }
}

// ---------------------------------------------------------------------------
// fp32 -> bf16 hi/lo split (elementwise, float4)
// ---------------------------------------------------------------------------
__global__ __launch_bounds__(256) void split_kernel(
    const float* __restrict__ in, __nv_bfloat16* __restrict__ hi,
    __nv_bfloat16* __restrict__ lo, int n4)
{
    int i = blockIdx.x * blockDim.x + threadIdx.x;
    if (i >= n4) return;
    float4 v = ((const float4*)in)[i];
    __nv_bfloat16 h[4], l[4];
    float f[4] = {v.x, v.y, v.z, v.w};
    #pragma unroll
    for (int j = 0; j < 4; j++) {
        h[j] = __float2bfloat16(f[j]);
        l[j] = __float2bfloat16(f[j] - __bfloat162float(h[j]));
    }
    ((ushort4*)hi)[i] = make_ushort4(__bfloat16_as_ushort(h[0]), __bfloat16_as_ushort(h[1]),
                                     __bfloat16_as_ushort(h[2]), __bfloat16_as_ushort(h[3]));
    ((ushort4*)lo)[i] = make_ushort4(__bfloat16_as_ushort(l[0]), __bfloat16_as_ushort(l[1]),
                                     __bfloat16_as_ushort(l[2]), __bfloat16_as_ushort(l[3]));
}

// ---------------------------------------------------------------------------
// fp32 [K][N] -> transposed bf16 hi/lo [N][K]
// ---------------------------------------------------------------------------
__global__ __launch_bounds__(256) void splitT_kernel(
    const float* __restrict__ w, __nv_bfloat16* __restrict__ thi,
    __nv_bfloat16* __restrict__ tlo, int K, int N)
{
    __shared__ float t[32][33];
    const int n0 = blockIdx.x * 32, k0 = blockIdx.y * 32;
    const int tx = threadIdx.x & 31, ty = threadIdx.x >> 5;
    #pragma unroll
    for (int j = ty; j < 32; j += 8)
        t[j][tx] = w[(size_t)(k0 + j) * N + n0 + tx];
    __syncthreads();
    #pragma unroll
    for (int j = ty; j < 32; j += 8) {
        float v = t[tx][j];
        __nv_bfloat16 h = __float2bfloat16(v);
        __nv_bfloat16 l = __float2bfloat16(v - __bfloat162float(h));
        thi[(size_t)(n0 + j) * K + k0 + tx] = h;
        tlo[(size_t)(n0 + j) * K + k0 + tx] = l;
    }
}

// ---------------------------------------------------------------------------
// HMMA flash attention, split-bf16 (unchanged — known-good).
// ---------------------------------------------------------------------------
#define AT_Q    0
#define AT_QL   16384
#define AT_ST   32768
#define AT_STB  32768
#define AT_KH   0
#define AT_KL   8192
#define AT_VH   16384
#define AT_VL   24576
#define AT_SMEM (AT_ST + 2 * AT_STB)   // 98304

__global__ __launch_bounds__(256, 1) void attn_mma(
    const __nv_bfloat16* __restrict__ qh, const __nv_bfloat16* __restrict__ ql,
    __nv_bfloat16* __restrict__ ohi, __nv_bfloat16* __restrict__ olo)
{
    extern __shared__ char sm[];
    const uint32_t sb = smem_u32(sm);
    const int tid  = threadIdx.x;
    const int lane = tid & 31;
    const int warp = tid >> 5;
    const int sub = lane >> 3, rin = lane & 7;
    const int g = lane >> 2, t = lane & 3;

    const int qt = blockIdx.x, head = blockIdx.y, batch = blockIdx.z;
    const size_t tok0 = (size_t)batch * SEQ;
    const size_t qbase = (tok0 + qt * 128) * QKVDIM + head * HDIM;

    #pragma unroll
    for (int j = 0; j < 4; j++) {
        int id = tid + j * 256;
        int r = id >> 3, c = id & 7;
        uint32_t sw = r * 128 + ((c ^ (r & 7)) << 4);
        size_t go = (size_t)r * QKVDIM * 2 + c * 16;
        cp_async16(sb + AT_Q  + sw, (const char*)(qh + qbase) + go);
        cp_async16(sb + AT_QL + sw, (const char*)(ql + qbase) + go);
    }
    CP_COMMIT();

    auto load_kv = [&](int s, int jt) {
        size_t kb = (tok0 + jt * 64) * QKVDIM + DIM + head * HDIM;
        size_t vb = kb + DIM;
        uint32_t st = sb + AT_ST + s * AT_STB;
        #pragma unroll
        for (int j = 0; j < 2; j++) {
            int id = tid + j * 256;
            int r = id >> 3, c = id & 7;
            uint32_t sw = r * 128 + ((c ^ (r & 7)) << 4);
            size_t go = (size_t)r * QKVDIM * 2 + c * 16;
            cp_async16(st + AT_KH + sw, (const char*)(qh + kb) + go);
            cp_async16(st + AT_KL + sw, (const char*)(ql + kb) + go);
            cp_async16(st + AT_VH + sw, (const char*)(qh + vb) + go);
            cp_async16(st + AT_VL + sw, (const char*)(ql + vb) + go);
        }
        CP_COMMIT();
    };

    load_kv(0, 0);
    load_kv(1, 1);

    CP_WAIT2();
    __syncthreads();
    uint32_t Qh[4][4], Ql[4][4];
    {
        int row = warp * 16 + (sub & 1) * 8 + rin;
        #pragma unroll
        for (int s4 = 0; s4 < 4; s4++) {
            int ch = 2 * s4 + (sub >> 1);
            uint32_t off = row * 128 + ((ch ^ (row & 7)) << 4);
            ldsm_x4(Qh[s4], sb + AT_Q  + off);
            ldsm_x4(Ql[s4], sb + AT_QL + off);
        }
    }

    float m0 = -1e30f, m1 = -1e30f, l0 = 0.f, l1 = 0.f;
    float O[8][4];
    #pragma unroll
    for (int b = 0; b < 8; b++)
        #pragma unroll
        for (int q = 0; q < 4; q++) O[b][q] = 0.f;

    for (int jt = 0; jt < SEQ / 64; jt++) {
        const int s = jt & 1;
        if (jt == SEQ / 64 - 1) { CP_WAIT0(); } else { CP_WAIT1(); }
        __syncthreads();
        const uint32_t stb = sb + AT_ST + s * AT_STB;

        float S[8][4];
        #pragma unroll
        for (int b = 0; b < 8; b++)
            #pragma unroll
            for (int q = 0; q < 4; q++) S[b][q] = 0.f;

        #pragma unroll
        for (int s4 = 0; s4 < 4; s4++) {
            int bch = 2 * s4 + (sub & 1);
            #pragma unroll
            for (int jp = 0; jp < 4; jp++) {
                int row = jp * 16 + (sub >> 1) * 8 + rin;
                uint32_t off = row * 128 + ((bch ^ (row & 7)) << 4);
                uint32_t kh[4], kl[4];
                ldsm_x4(kh, stb + AT_KH + off);
                ldsm_x4(kl, stb + AT_KL + off);
                mma_bf16(S[2*jp],   Qh[s4], kh);
                mma_bf16(S[2*jp],   Qh[s4], kl);
                mma_bf16(S[2*jp],   Ql[s4], kh);
                mma_bf16(S[2*jp+1], Qh[s4], kh + 2);
                mma_bf16(S[2*jp+1], Qh[s4], kl + 2);
                mma_bf16(S[2*jp+1], Ql[s4], kh + 2);
            }
        }

        float mx0 = -1e30f, mx1 = -1e30f;
        #pragma unroll
        for (int b = 0; b < 8; b++) {
            #pragma unroll
            for (int q = 0; q < 4; q++) S[b][q] *= SCALE;
            mx0 = fmaxf(mx0, fmaxf(S[b][0], S[b][1]));
            mx1 = fmaxf(mx1, fmaxf(S[b][2], S[b][3]));
        }
        #pragma unroll
        for (int off = 1; off < 4; off <<= 1) {
            mx0 = fmaxf(mx0, __shfl_xor_sync(0xffffffffu, mx0, off));
            mx1 = fmaxf(mx1, __shfl_xor_sync(0xffffffffu, mx1, off));
        }
        float mn0 = fmaxf(m0, mx0), mn1 = fmaxf(m1, mx1);
        float al0 = __expf(m0 - mn0), al1 = __expf(m1 - mn1);
        m0 = mn0; m1 = mn1;

        float rs0 = 0.f, rs1 = 0.f;
        #pragma unroll
        for (int b = 0; b < 8; b++) {
            S[b][0] = __expf(S[b][0] - mn0); rs0 += S[b][0];
            S[b][1] = __expf(S[b][1] - mn0); rs0 += S[b][1];
            S[b][2] = __expf(S[b][2] - mn1); rs1 += S[b][2];
            S[b][3] = __expf(S[b][3] - mn1); rs1 += S[b][3];
        }
        #pragma unroll
        for (int off = 1; off < 4; off <<= 1) {
            rs0 += __shfl_xor_sync(0xffffffffu, rs0, off);
            rs1 += __shfl_xor_sync(0xffffffffu, rs1, off);
        }
        l0 = l0 * al0 + rs0;
        l1 = l1 * al1 + rs1;
        #pragma unroll
        for (int b = 0; b < 8; b++) {
            O[b][0] *= al0; O[b][1] *= al0;
            O[b][2] *= al1; O[b][3] *= al1;
        }

        #pragma unroll
        for (int a = 0; a < 4; a++) {
            uint32_t Ph[4], Pl[4];
            Ph[0] = pack_bf16(S[2*a][0],   S[2*a][1]);
            Ph[1] = pack_bf16(S[2*a][2],   S[2*a][3]);
            Ph[2] = pack_bf16(S[2*a+1][0], S[2*a+1][1]);
            Ph[3] = pack_bf16(S[2*a+1][2], S[2*a+1][3]);
            Pl[0] = resid_bf16(Ph[0], S[2*a][0],   S[2*a][1]);
            Pl[1] = resid_bf16(Ph[1], S[2*a][2],   S[2*a][3]);
            Pl[2] = resid_bf16(Ph[2], S[2*a+1][0], S[2*a+1][1]);
            Pl[3] = resid_bf16(Ph[3], S[2*a+1][2], S[2*a+1][3]);

            int vrow = a * 16 + (sub & 1) * 8 + rin;
            #pragma unroll
            for (int bp = 0; bp < 4; bp++) {
                int ch = 2 * bp + (sub >> 1);
                uint32_t off = vrow * 128 + ((ch ^ (vrow & 7)) << 4);
                uint32_t vh[4], vl[4];
                ldsm_x4_t(vh, stb + AT_VH + off);
                ldsm_x4_t(vl, stb + AT_VL + off);
                mma_bf16(O[2*bp],   Ph, vh);
                mma_bf16(O[2*bp],   Ph, vl);
                mma_bf16(O[2*bp],   Pl, vh);
                mma_bf16(O[2*bp+1], Ph, vh + 2);
                mma_bf16(O[2*bp+1], Ph, vl + 2);
                mma_bf16(O[2*bp+1], Pl, vh + 2);
            }
        }
        __syncthreads();
        if (jt + 2 < SEQ / 64) load_kv(s, jt + 2);
    }

    float inv0 = 1.f / l0, inv1 = 1.f / l1;
    size_t t0 = tok0 + qt * 128 + warp * 16 + g;
    size_t t1 = t0 + 8;
    #pragma unroll
    for (int b = 0; b < 8; b++) {
        int col = head * HDIM + b * 8 + 2 * t;
        float o00 = O[b][0] * inv0, o01 = O[b][1] * inv0;
        float o10 = O[b][2] * inv1, o11 = O[b][3] * inv1;
        uint32_t hp0 = pack_bf16(o00, o01);
        uint32_t hp1 = pack_bf16(o10, o11);
        *(uint32_t*)&ohi[t0 * DIM + col] = hp0;
        *(uint32_t*)&ohi[t1 * DIM + col] = hp1;
        *(uint32_t*)&olo[t0 * DIM + col] = resid_bf16(hp0, o00, o01);
        *(uint32_t*)&olo[t1 * DIM + col] = resid_bf16(hp1, o10, o11);
    }
}

// ----------------------------------------------------------------------------
// Launch
// ----------------------------------------------------------------------------
extern "C" void kernel_launch(void* const* d_in, const int* in_sizes, int n_in,
                              void* d_out, int out_size)
{
    const float* x     = (const float*)d_in[0];
    const float* w_qkv = (const float*)d_in[1];
    const float* w_out = (const float*)d_in[2];
    const float* b_out = (const float*)d_in[3];
    float* out = (float*)d_out;

    void *p_xhi, *p_xlo, *p_w1hi, *p_w1lo, *p_w2hi, *p_w2lo,
         *p_qh, *p_ql, *p_ahi, *p_alo;
    cudaGetSymbolAddress(&p_xhi, g_xhi);
    cudaGetSymbolAddress(&p_xlo, g_xlo);
    cudaGetSymbolAddress(&p_w1hi, g_w1hi);
    cudaGetSymbolAddress(&p_w1lo, g_w1lo);
    cudaGetSymbolAddress(&p_w2hi, g_w2hi);
    cudaGetSymbolAddress(&p_w2lo, g_w2lo);
    cudaGetSymbolAddress(&p_qh, g_qkvhi);
    cudaGetSymbolAddress(&p_ql, g_qkvlo);
    cudaGetSymbolAddress(&p_ahi, g_ahi);
    cudaGetSymbolAddress(&p_alo, g_alo);

    cudaFuncSetAttribute(gemm_mma<0>, cudaFuncAttributeMaxDynamicSharedMemorySize, GEMM_SMEM);
    cudaFuncSetAttribute(gemm_mma<1>, cudaFuncAttributeMaxDynamicSharedMemorySize, GEMM_SMEM);
    cudaFuncSetAttribute(attn_mma,    cudaFuncAttributeMaxDynamicSharedMemorySize, AT_SMEM);

    // 0) split inputs / weights into bf16 hi+lo
    split_kernel<<<(TOKENS * DIM / 4 + 255) / 256, 256>>>(
        x, (__nv_bfloat16*)p_xhi, (__nv_bfloat16*)p_xlo, TOKENS * DIM / 4);
    splitT_kernel<<<dim3(QKVDIM / 32, DIM / 32), 256>>>(
        w_qkv, (__nv_bfloat16*)p_w1hi, (__nv_bfloat16*)p_w1lo, DIM, QKVDIM);
    splitT_kernel<<<dim3(DIM / 32, DIM / 32), 256>>>(
        w_out, (__nv_bfloat16*)p_w2hi, (__nv_bfloat16*)p_w2lo, DIM, DIM);

    // 1) qkv = x @ w_qkv -> bf16 hi/lo directly     [8192, 3072]
    gemm_mma<1><<<dim3(QKVDIM / 128, TOKENS / 128), 256, GEMM_SMEM>>>(
        (const __nv_bfloat16*)p_xhi, (const __nv_bfloat16*)p_xlo,
        (const __nv_bfloat16*)p_w1hi, (const __nv_bfloat16*)p_w1lo,
        nullptr, nullptr,
        (__nv_bfloat16*)p_qh, (__nv_bfloat16*)p_ql, QKVDIM);

    // 2) attention -> bf16 hi/lo directly            [8192, 1024]
    attn_mma<<<dim3(SEQ / 128, HEADS, BATCH), 256, AT_SMEM>>>(
        (const __nv_bfloat16*)p_qh, (const __nv_bfloat16*)p_ql,
        (__nv_bfloat16*)p_ahi, (__nv_bfloat16*)p_alo);

    // 3) out = attn @ w_out + b                      [8192, 1024]
    gemm_mma<0><<<dim3(DIM / 128, TOKENS / 128), 256, GEMM_SMEM>>>(
        (const __nv_bfloat16*)p_ahi, (const __nv_bfloat16*)p_alo,
        (const __nv_bfloat16*)p_w2hi, (const __nv_bfloat16*)p_w2lo,
        b_out, out, nullptr, nullptr, DIM);
}

// round 8
// speedup vs baseline: 1.3795x; 1.1807x over previous
#include <cuda_runtime.h>
#include <cuda_fp16.h>
#include <cstdint>

// Problem constants
#define BATCH  8
#define SEQ    1024
#define DIM    1024
#define HEADS  16
#define HDIM   64
#define TOKENS (BATCH * SEQ)          // 8192
#define QKVDIM (3 * DIM)              // 3072
#define SCALE  0.03125f               // 1024^-0.5

// ---------------------------------------------------------------------------
// Scratch (device globals: allocation-guard safe) — all fp16 hi/lo pairs
// ---------------------------------------------------------------------------
__device__ __half g_xhi[(size_t)TOKENS * DIM];
__device__ __half g_xlo[(size_t)TOKENS * DIM];
__device__ __half g_w1hi[(size_t)QKVDIM * DIM];      // w_qkv^T [3072][1024]
__device__ __half g_w1lo[(size_t)QKVDIM * DIM];
__device__ __half g_w2hi[(size_t)DIM * DIM];         // w_out^T [1024][1024]
__device__ __half g_w2lo[(size_t)DIM * DIM];
__device__ __half g_qkvhi[(size_t)TOKENS * QKVDIM];  // qkv hi [8192][3072]
__device__ __half g_qkvlo[(size_t)TOKENS * QKVDIM];
__device__ __half g_ahi[(size_t)TOKENS * DIM];
__device__ __half g_alo[(size_t)TOKENS * DIM];

// ---------------------------------------------------------------------------
// Helpers
// ---------------------------------------------------------------------------
__device__ __forceinline__ uint32_t smem_u32(const void* p) {
    uint32_t a;
    asm("{ .reg .u64 t; cvta.to.shared.u64 t, %1; cvt.u32.u64 %0, t; }" : "=r"(a) : "l"(p));
    return a;
}

__device__ __forceinline__ void cp_async16(uint32_t dst, const void* src) {
    asm volatile("cp.async.cg.shared.global [%0], [%1], 16;\n" :: "r"(dst), "l"(src));
}
#define CP_COMMIT() asm volatile("cp.async.commit_group;\n" ::: "memory")
#define CP_WAIT2()  asm volatile("cp.async.wait_group 2;\n" ::: "memory")
#define CP_WAIT1()  asm volatile("cp.async.wait_group 1;\n" ::: "memory")
#define CP_WAIT0()  asm volatile("cp.async.wait_group 0;\n" ::: "memory")

__device__ __forceinline__ void ldsm_x4(uint32_t* r, uint32_t addr) {
    asm volatile("ldmatrix.sync.aligned.m8n8.x4.shared.b16 {%0,%1,%2,%3}, [%4];"
                 : "=r"(r[0]), "=r"(r[1]), "=r"(r[2]), "=r"(r[3]) : "r"(addr));
}

__device__ __forceinline__ void ldsm_x4_t(uint32_t* r, uint32_t addr) {
    asm volatile("ldmatrix.sync.aligned.m8n8.x4.trans.shared.b16 {%0,%1,%2,%3}, [%4];"
                 : "=r"(r[0]), "=r"(r[1]), "=r"(r[2]), "=r"(r[3]) : "r"(addr));
}

// fp16 HMMA, fp32 accumulate
__device__ __forceinline__ void mma_f16(float* d, const uint32_t* a, const uint32_t* b) {
    asm volatile("mma.sync.aligned.m16n8k16.row.col.f32.f16.f16.f32 "
                 "{%0,%1,%2,%3}, {%4,%5,%6,%7}, {%8,%9}, {%0,%1,%2,%3};"
                 : "+f"(d[0]), "+f"(d[1]), "+f"(d[2]), "+f"(d[3])
                 : "r"(a[0]), "r"(a[1]), "r"(a[2]), "r"(a[3]), "r"(b[0]), "r"(b[1]));
}

// pack two fp32 into f16x2 (lo -> low half)
__device__ __forceinline__ uint32_t pack_f16(float lo, float hi) {
    uint32_t d;
    asm("cvt.rn.f16x2.f32 %0, %1, %2;" : "=r"(d) : "f"(hi), "f"(lo));
    return d;
}
// residual pair after fp16 truncation of (lo, hi) packed in hp
__device__ __forceinline__ uint32_t resid_f16(uint32_t hp, float lo, float hi) {
    __half2 h = *reinterpret_cast<__half2*>(&hp);
    return pack_f16(lo - __half2float(__low2half(h)),
                    hi - __half2float(__high2half(h)));
}

// ---------------------------------------------------------------------------
// Split-fp16 HMMA GEMM (2-pass): C = (Ahi+Alo)[M,K] @ Whi[N,K]^T
// OUT==0: write fp32 C (+bias).  OUT==1: write fp16 hi/lo pair (Chi, Clo).
// Block 128x128, BK=32, 256 threads (8 warps, 2x4 grid of 64x32 warp tiles).
// 3-stage cp.async pipeline (one barrier per BK iter), XOR-swizzled smem,
// pass-major mma ordering.
// ---------------------------------------------------------------------------
#define GK     1024
#define BK     32
#define NITER  (GK / BK)               // 32
#define TILEB  (128 * 64)              // [128 rows][32 f16 = 64B]
#define STAGEB (3 * TILEB)             // 24 KB (Ahi, Alo, Whi)
#define NSTAGE 3
#define GEMM_SMEM (NSTAGE * STAGEB)    // 72 KB

template<int OUT>
__global__ __launch_bounds__(256, 2) void gemm_mma(
    const __half* __restrict__ Ahi, const __half* __restrict__ Alo,
    const __half* __restrict__ Whi,
    const float* __restrict__ bias, float* __restrict__ C,
    __half* __restrict__ Chi, __half* __restrict__ Clo, int N)
{
    extern __shared__ char sm[];
    const uint32_t sbase = smem_u32(sm);
    const int tid  = threadIdx.x;
    const int lane = tid & 31;
    const int warp = tid >> 5;
    const int wm = warp & 1;
    const int wn = warp >> 1;
    const int m0 = blockIdx.y * 128;
    const int n0 = blockIdx.x * 128;

    float acc[4][4][4];
    #pragma unroll
    for (int i = 0; i < 4; i++)
        #pragma unroll
        for (int j = 0; j < 4; j++)
            #pragma unroll
            for (int q = 0; q < 4; q++) acc[i][j][q] = 0.f;

    const __half* gs[3] = {Ahi, Alo, Whi};
    const int r0s[3] = {m0, m0, n0};

    auto soff = [&](int s, int t) -> uint32_t { return sbase + s * STAGEB + t * TILEB; };

    auto load_stage = [&](int s, int k0) {
        #pragma unroll
        for (int t = 0; t < 3; t++) {
            const char* gp = (const char*)(gs[t] + (size_t)r0s[t] * GK + k0);
            #pragma unroll
            for (int j = 0; j < 2; j++) {
                int id = tid + j * 256;
                int r = id >> 2, c = id & 3;
                uint32_t sw = r * 64 + ((c ^ ((r >> 1) & 3)) << 4);
                cp_async16(soff(s, t) + sw, gp + (size_t)r * (GK * 2) + c * 16);
            }
        }
        CP_COMMIT();
    };

    load_stage(0, 0);
    load_stage(1, BK);

    const int sub = lane >> 3, rin = lane & 7;
    const int a_row_off = (sub & 1) * 8 + rin;
    const int a_chunk   = sub >> 1;
    const int b_row_off = (sub >> 1) * 8 + rin;
    const int b_chunk   = sub & 1;

    for (int it = 0; it < NITER; it++) {
        const int s = it % NSTAGE;
        if (it == NITER - 1) { CP_WAIT0(); } else { CP_WAIT1(); }
        __syncthreads();   // stage s visible; stage (it-1)%3 fully drained

        const uint32_t aH = soff(s, 0), aL = soff(s, 1), wH = soff(s, 2);

        #pragma unroll
        for (int ks = 0; ks < 2; ks++) {
            uint32_t Ah[4][4], Al[4][4], Bh[4][2];

            #pragma unroll
            for (int mi = 0; mi < 4; mi++) {
                int row = wm * 64 + mi * 16 + a_row_off;
                int c = ks * 2 + a_chunk;
                uint32_t off = row * 64 + ((c ^ ((row >> 1) & 3)) << 4);
                ldsm_x4(Ah[mi], aH + off);
                ldsm_x4(Al[mi], aL + off);
            }
            #pragma unroll
            for (int p = 0; p < 2; p++) {
                int row = wn * 32 + p * 16 + b_row_off;
                int c = ks * 2 + b_chunk;
                uint32_t off = row * 64 + ((c ^ ((row >> 1) & 3)) << 4);
                uint32_t t0[4];
                ldsm_x4(t0, wH + off);
                Bh[p*2  ][0] = t0[0]; Bh[p*2  ][1] = t0[1];
                Bh[p*2+1][0] = t0[2]; Bh[p*2+1][1] = t0[3];
            }

            // pass-major: 16 independent accumulators per pass
            #pragma unroll
            for (int mi = 0; mi < 4; mi++)
                #pragma unroll
                for (int ni = 0; ni < 4; ni++)
                    mma_f16(acc[mi][ni], Ah[mi], Bh[ni]);   // hi*hi
            #pragma unroll
            for (int mi = 0; mi < 4; mi++)
                #pragma unroll
                for (int ni = 0; ni < 4; ni++)
                    mma_f16(acc[mi][ni], Al[mi], Bh[ni]);   // lo*hi
        }
        if (it + 2 < NITER) load_stage((it + 2) % NSTAGE, (it + 2) * BK);
    }

    const int g = lane >> 2, c2 = (lane & 3) * 2;
    #pragma unroll
    for (int mi = 0; mi < 4; mi++) {
        int row = m0 + wm * 64 + mi * 16 + g;
        #pragma unroll
        for (int ni = 0; ni < 4; ni++) {
            int col = n0 + wn * 32 + ni * 8 + c2;
            if (OUT == 0) {
                float b0 = 0.f, b1 = 0.f;
                if (bias) { b0 = bias[col]; b1 = bias[col + 1]; }
                float2 v0 = make_float2(acc[mi][ni][0] + b0, acc[mi][ni][1] + b1);
                float2 v1 = make_float2(acc[mi][ni][2] + b0, acc[mi][ni][3] + b1);
                *(float2*)&C[(size_t)row * N + col] = v0;
                *(float2*)&C[(size_t)(row + 8) * N + col] = v1;
            } else {
                uint32_t hp0 = pack_f16(acc[mi][ni][0], acc[mi][ni][1]);
                uint32_t hp1 = pack_f16(acc[mi][ni][2], acc[mi][ni][3]);
                uint32_t lp0 = resid_f16(hp0, acc[mi][ni][0], acc[mi][ni][1]);
                uint32_t lp1 = resid_f16(hp1, acc[mi][ni][2], acc[mi][ni][3]);
                *(uint32_t*)&Chi[(size_t)row * N + col] = hp0;
                *(uint32_t*)&Chi[(size_t)(row + 8) * N + col] = hp1;
                *(uint32_t*)&Clo[(size_t)row * N + col] = lp0;
                *(uint32_t*)&Clo[(size_t)(row + 8) * N + col] = lp1;
            }
        }
    }
}

// ---------------------------------------------------------------------------
// fp32 -> fp16 hi/lo split (elementwise, float4)
// ---------------------------------------------------------------------------
__global__ __launch_bounds__(256) void split_kernel(
    const float* __restrict__ in, __half* __restrict__ hi,
    __half* __restrict__ lo, int n4)
{
    int i = blockIdx.x * blockDim.x + threadIdx.x;
    if (i >= n4) return;
    float4 v = ((const float4*)in)[i];
    __half h[4], l[4];
    float f[4] = {v.x, v.y, v.z, v.w};
    #pragma unroll
    for (int j = 0; j < 4; j++) {
        h[j] = __float2half_rn(f[j]);
        l[j] = __float2half_rn(f[j] - __half2float(h[j]));
    }
    ((ushort4*)hi)[i] = make_ushort4(__half_as_ushort(h[0]), __half_as_ushort(h[1]),
                                     __half_as_ushort(h[2]), __half_as_ushort(h[3]));
    ((ushort4*)lo)[i] = make_ushort4(__half_as_ushort(l[0]), __half_as_ushort(l[1]),
                                     __half_as_ushort(l[2]), __half_as_ushort(l[3]));
}

// ---------------------------------------------------------------------------
// fp32 [K][N] -> transposed fp16 hi/lo [N][K]
// ---------------------------------------------------------------------------
__global__ __launch_bounds__(256) void splitT_kernel(
    const float* __restrict__ w, __half* __restrict__ thi,
    __half* __restrict__ tlo, int K, int N)
{
    __shared__ float t[32][33];
    const int n0 = blockIdx.x * 32, k0 = blockIdx.y * 32;
    const int tx = threadIdx.x & 31, ty = threadIdx.x >> 5;
    #pragma unroll
    for (int j = ty; j < 32; j += 8)
        t[j][tx] = w[(size_t)(k0 + j) * N + n0 + tx];
    __syncthreads();
    #pragma unroll
    for (int j = ty; j < 32; j += 8) {
        float v = t[tx][j];
        __half h = __float2half_rn(v);
        __half l = __float2half_rn(v - __half2float(h));
        thi[(size_t)(n0 + j) * K + k0 + tx] = h;
        tlo[(size_t)(n0 + j) * K + k0 + tx] = l;
    }
}

// ---------------------------------------------------------------------------
// HMMA flash attention, split-fp16, 3-pass (error ~2^-22, negligible).
// Structure unchanged from the known-good bf16 version.
// ---------------------------------------------------------------------------
#define AT_Q    0
#define AT_QL   16384
#define AT_ST   32768
#define AT_STB  32768
#define AT_KH   0
#define AT_KL   8192
#define AT_VH   16384
#define AT_VL   24576
#define AT_SMEM (AT_ST + 2 * AT_STB)   // 98304

__global__ __launch_bounds__(256, 1) void attn_mma(
    const __half* __restrict__ qh, const __half* __restrict__ ql,
    __half* __restrict__ ohi, __half* __restrict__ olo)
{
    extern __shared__ char sm[];
    const uint32_t sb = smem_u32(sm);
    const int tid  = threadIdx.x;
    const int lane = tid & 31;
    const int warp = tid >> 5;
    const int sub = lane >> 3, rin = lane & 7;
    const int g = lane >> 2, t = lane & 3;

    const int qt = blockIdx.x, head = blockIdx.y, batch = blockIdx.z;
    const size_t tok0 = (size_t)batch * SEQ;
    const size_t qbase = (tok0 + qt * 128) * QKVDIM + head * HDIM;

    #pragma unroll
    for (int j = 0; j < 4; j++) {
        int id = tid + j * 256;
        int r = id >> 3, c = id & 7;
        uint32_t sw = r * 128 + ((c ^ (r & 7)) << 4);
        size_t go = (size_t)r * QKVDIM * 2 + c * 16;
        cp_async16(sb + AT_Q  + sw, (const char*)(qh + qbase) + go);
        cp_async16(sb + AT_QL + sw, (const char*)(ql + qbase) + go);
    }
    CP_COMMIT();

    auto load_kv = [&](int s, int jt) {
        size_t kb = (tok0 + jt * 64) * QKVDIM + DIM + head * HDIM;
        size_t vb = kb + DIM;
        uint32_t st = sb + AT_ST + s * AT_STB;
        #pragma unroll
        for (int j = 0; j < 2; j++) {
            int id = tid + j * 256;
            int r = id >> 3, c = id & 7;
            uint32_t sw = r * 128 + ((c ^ (r & 7)) << 4);
            size_t go = (size_t)r * QKVDIM * 2 + c * 16;
            cp_async16(st + AT_KH + sw, (const char*)(qh + kb) + go);
            cp_async16(st + AT_KL + sw, (const char*)(ql + kb) + go);
            cp_async16(st + AT_VH + sw, (const char*)(qh + vb) + go);
            cp_async16(st + AT_VL + sw, (const char*)(ql + vb) + go);
        }
        CP_COMMIT();
    };

    load_kv(0, 0);
    load_kv(1, 1);

    CP_WAIT2();
    __syncthreads();
    uint32_t Qh[4][4], Ql[4][4];
    {
        int row = warp * 16 + (sub & 1) * 8 + rin;
        #pragma unroll
        for (int s4 = 0; s4 < 4; s4++) {
            int ch = 2 * s4 + (sub >> 1);
            uint32_t off = row * 128 + ((ch ^ (row & 7)) << 4);
            ldsm_x4(Qh[s4], sb + AT_Q  + off);
            ldsm_x4(Ql[s4], sb + AT_QL + off);
        }
    }

    float m0 = -1e30f, m1 = -1e30f, l0 = 0.f, l1 = 0.f;
    float O[8][4];
    #pragma unroll
    for (int b = 0; b < 8; b++)
        #pragma unroll
        for (int q = 0; q < 4; q++) O[b][q] = 0.f;

    for (int jt = 0; jt < SEQ / 64; jt++) {
        const int s = jt & 1;
        if (jt == SEQ / 64 - 1) { CP_WAIT0(); } else { CP_WAIT1(); }
        __syncthreads();
        const uint32_t stb = sb + AT_ST + s * AT_STB;

        float S[8][4];
        #pragma unroll
        for (int b = 0; b < 8; b++)
            #pragma unroll
            for (int q = 0; q < 4; q++) S[b][q] = 0.f;

        #pragma unroll
        for (int s4 = 0; s4 < 4; s4++) {
            int bch = 2 * s4 + (sub & 1);
            #pragma unroll
            for (int jp = 0; jp < 4; jp++) {
                int row = jp * 16 + (sub >> 1) * 8 + rin;
                uint32_t off = row * 128 + ((bch ^ (row & 7)) << 4);
                uint32_t kh[4], kl[4];
                ldsm_x4(kh, stb + AT_KH + off);
                ldsm_x4(kl, stb + AT_KL + off);
                mma_f16(S[2*jp],   Qh[s4], kh);
                mma_f16(S[2*jp],   Qh[s4], kl);
                mma_f16(S[2*jp],   Ql[s4], kh);
                mma_f16(S[2*jp+1], Qh[s4], kh + 2);
                mma_f16(S[2*jp+1], Qh[s4], kl + 2);
                mma_f16(S[2*jp+1], Ql[s4], kh + 2);
            }
        }

        float mx0 = -1e30f, mx1 = -1e30f;
        #pragma unroll
        for (int b = 0; b < 8; b++) {
            #pragma unroll
            for (int q = 0; q < 4; q++) S[b][q] *= SCALE;
            mx0 = fmaxf(mx0, fmaxf(S[b][0], S[b][1]));
            mx1 = fmaxf(mx1, fmaxf(S[b][2], S[b][3]));
        }
        #pragma unroll
        for (int off = 1; off < 4; off <<= 1) {
            mx0 = fmaxf(mx0, __shfl_xor_sync(0xffffffffu, mx0, off));
            mx1 = fmaxf(mx1, __shfl_xor_sync(0xffffffffu, mx1, off));
        }
        float mn0 = fmaxf(m0, mx0), mn1 = fmaxf(m1, mx1);
        float al0 = __expf(m0 - mn0), al1 = __expf(m1 - mn1);
        m0 = mn0; m1 = mn1;

        float rs0 = 0.f, rs1 = 0.f;
        #pragma unroll
        for (int b = 0; b < 8; b++) {
            S[b][0] = __expf(S[b][0] - mn0); rs0 += S[b][0];
            S[b][1] = __expf(S[b][1] - mn0); rs0 += S[b][1];
            S[b][2] = __expf(S[b][2] - mn1); rs1 += S[b][2];
            S[b][3] = __expf(S[b][3] - mn1); rs1 += S[b][3];
        }
        #pragma unroll
        for (int off = 1; off < 4; off <<= 1) {
            rs0 += __shfl_xor_sync(0xffffffffu, rs0, off);
            rs1 += __shfl_xor_sync(0xffffffffu, rs1, off);
        }
        l0 = l0 * al0 + rs0;
        l1 = l1 * al1 + rs1;
        #pragma unroll
        for (int b = 0; b < 8; b++) {
            O[b][0] *= al0; O[b][1] *= al0;
            O[b][2] *= al1; O[b][3] *= al1;
        }

        #pragma unroll
        for (int a = 0; a < 4; a++) {
            uint32_t Ph[4], Pl[4];
            Ph[0] = pack_f16(S[2*a][0],   S[2*a][1]);
            Ph[1] = pack_f16(S[2*a][2],   S[2*a][3]);
            Ph[2] = pack_f16(S[2*a+1][0], S[2*a+1][1]);
            Ph[3] = pack_f16(S[2*a+1][2], S[2*a+1][3]);
            Pl[0] = resid_f16(Ph[0], S[2*a][0],   S[2*a][1]);
            Pl[1] = resid_f16(Ph[1], S[2*a][2],   S[2*a][3]);
            Pl[2] = resid_f16(Ph[2], S[2*a+1][0], S[2*a+1][1]);
            Pl[3] = resid_f16(Ph[3], S[2*a+1][2], S[2*a+1][3]);

            int vrow = a * 16 + (sub & 1) * 8 + rin;
            #pragma unroll
            for (int bp = 0; bp < 4; bp++) {
                int ch = 2 * bp + (sub >> 1);
                uint32_t off = vrow * 128 + ((ch ^ (vrow & 7)) << 4);
                uint32_t vh[4], vl[4];
                ldsm_x4_t(vh, stb + AT_VH + off);
                ldsm_x4_t(vl, stb + AT_VL + off);
                mma_f16(O[2*bp],   Ph, vh);
                mma_f16(O[2*bp],   Ph, vl);
                mma_f16(O[2*bp],   Pl, vh);
                mma_f16(O[2*bp+1], Ph, vh + 2);
                mma_f16(O[2*bp+1], Ph, vl + 2);
                mma_f16(O[2*bp+1], Pl, vh + 2);
            }
        }
        __syncthreads();
        if (jt + 2 < SEQ / 64) load_kv(s, jt + 2);
    }

    float inv0 = 1.f / l0, inv1 = 1.f / l1;
    size_t t0 = tok0 + qt * 128 + warp * 16 + g;
    size_t t1 = t0 + 8;
    #pragma unroll
    for (int b = 0; b < 8; b++) {
        int col = head * HDIM + b * 8 + 2 * t;
        float o00 = O[b][0] * inv0, o01 = O[b][1] * inv0;
        float o10 = O[b][2] * inv1, o11 = O[b][3] * inv1;
        uint32_t hp0 = pack_f16(o00, o01);
        uint32_t hp1 = pack_f16(o10, o11);
        *(uint32_t*)&ohi[t0 * DIM + col] = hp0;
        *(uint32_t*)&ohi[t1 * DIM + col] = hp1;
        *(uint32_t*)&olo[t0 * DIM + col] = resid_f16(hp0, o00, o01);
        *(uint32_t*)&olo[t1 * DIM + col] = resid_f16(hp1, o10, o11);
    }
}

// ----------------------------------------------------------------------------
// Launch
// ----------------------------------------------------------------------------
extern "C" void kernel_launch(void* const* d_in, const int* in_sizes, int n_in,
                              void* d_out, int out_size)
{
    const float* x     = (const float*)d_in[0];
    const float* w_qkv = (const float*)d_in[1];
    const float* w_out = (const float*)d_in[2];
    const float* b_out = (const float*)d_in[3];
    float* out = (float*)d_out;

    void *p_xhi, *p_xlo, *p_w1hi, *p_w1lo, *p_w2hi, *p_w2lo,
         *p_qh, *p_ql, *p_ahi, *p_alo;
    cudaGetSymbolAddress(&p_xhi, g_xhi);
    cudaGetSymbolAddress(&p_xlo, g_xlo);
    cudaGetSymbolAddress(&p_w1hi, g_w1hi);
    cudaGetSymbolAddress(&p_w1lo, g_w1lo);
    cudaGetSymbolAddress(&p_w2hi, g_w2hi);
    cudaGetSymbolAddress(&p_w2lo, g_w2lo);
    cudaGetSymbolAddress(&p_qh, g_qkvhi);
    cudaGetSymbolAddress(&p_ql, g_qkvlo);
    cudaGetSymbolAddress(&p_ahi, g_ahi);
    cudaGetSymbolAddress(&p_alo, g_alo);

    cudaFuncSetAttribute(gemm_mma<0>, cudaFuncAttributeMaxDynamicSharedMemorySize, GEMM_SMEM);
    cudaFuncSetAttribute(gemm_mma<1>, cudaFuncAttributeMaxDynamicSharedMemorySize, GEMM_SMEM);
    cudaFuncSetAttribute(attn_mma,    cudaFuncAttributeMaxDynamicSharedMemorySize, AT_SMEM);

    // 0) split inputs / weights into fp16 hi+lo
    split_kernel<<<(TOKENS * DIM / 4 + 255) / 256, 256>>>(
        x, (__half*)p_xhi, (__half*)p_xlo, TOKENS * DIM / 4);
    splitT_kernel<<<dim3(QKVDIM / 32, DIM / 32), 256>>>(
        w_qkv, (__half*)p_w1hi, (__half*)p_w1lo, DIM, QKVDIM);
    splitT_kernel<<<dim3(DIM / 32, DIM / 32), 256>>>(
        w_out, (__half*)p_w2hi, (__half*)p_w2lo, DIM, DIM);

    // 1) qkv = x @ w_qkv -> fp16 hi/lo directly (2-pass)   [8192, 3072]
    gemm_mma<1><<<dim3(QKVDIM / 128, TOKENS / 128), 256, GEMM_SMEM>>>(
        (const __half*)p_xhi, (const __half*)p_xlo,
        (const __half*)p_w1hi,
        nullptr, nullptr,
        (__half*)p_qh, (__half*)p_ql, QKVDIM);

    // 2) attention -> fp16 hi/lo directly (3-pass)          [8192, 1024]
    attn_mma<<<dim3(SEQ / 128, HEADS, BATCH), 256, AT_SMEM>>>(
        (const __half*)p_qh, (const __half*)p_ql,
        (__half*)p_ahi, (__half*)p_alo);

    // 3) out = attn @ w_out + b (2-pass)                    [8192, 1024]
    gemm_mma<0><<<dim3(DIM / 128, TOKENS / 128), 256, GEMM_SMEM>>>(
        (const __half*)p_ahi, (const __half*)p_alo,
        (const __half*)p_w2hi,
        b_out, out, nullptr, nullptr, DIM);
}

// round 9
// speedup vs baseline: 1.6770x; 1.2157x over previous
#include <cuda_runtime.h>
#include <cuda_fp16.h>
#include <cstdint>

// Problem constants
#define BATCH  8
#define SEQ    1024
#define DIM    1024
#define HEADS  16
#define HDIM   64
#define TOKENS (BATCH * SEQ)          // 8192
#define QKVDIM (3 * DIM)              // 3072
#define SCALE  0.03125f               // 1024^-0.5

// ---------------------------------------------------------------------------
// Scratch (device globals: allocation-guard safe)
// ---------------------------------------------------------------------------
__device__ __half g_xhi[(size_t)TOKENS * DIM];
__device__ __half g_xlo[(size_t)TOKENS * DIM];
__device__ __half g_w1hi[(size_t)QKVDIM * DIM];      // w_qkv^T [3072][1024]
__device__ __half g_w2hi[(size_t)DIM * DIM];         // w_out^T [1024][1024]
__device__ __half g_w2lo[(size_t)DIM * DIM];
__device__ __half g_qkvhi[(size_t)TOKENS * QKVDIM];  // qkv hi [8192][3072]
__device__ __half g_ahi[(size_t)TOKENS * DIM];
__device__ __half g_alo[(size_t)TOKENS * DIM];

// ---------------------------------------------------------------------------
// Helpers
// ---------------------------------------------------------------------------
__device__ __forceinline__ uint32_t smem_u32(const void* p) {
    uint32_t a;
    asm("{ .reg .u64 t; cvta.to.shared.u64 t, %1; cvt.u32.u64 %0, t; }" : "=r"(a) : "l"(p));
    return a;
}

__device__ __forceinline__ void cp_async16(uint32_t dst, const void* src) {
    asm volatile("cp.async.cg.shared.global [%0], [%1], 16;\n" :: "r"(dst), "l"(src));
}
#define CP_COMMIT() asm volatile("cp.async.commit_group;\n" ::: "memory")
#define CP_WAIT2()  asm volatile("cp.async.wait_group 2;\n" ::: "memory")
#define CP_WAIT1()  asm volatile("cp.async.wait_group 1;\n" ::: "memory")
#define CP_WAIT0()  asm volatile("cp.async.wait_group 0;\n" ::: "memory")

__device__ __forceinline__ void ldsm_x4(uint32_t* r, uint32_t addr) {
    asm volatile("ldmatrix.sync.aligned.m8n8.x4.shared.b16 {%0,%1,%2,%3}, [%4];"
                 : "=r"(r[0]), "=r"(r[1]), "=r"(r[2]), "=r"(r[3]) : "r"(addr));
}

__device__ __forceinline__ void ldsm_x4_t(uint32_t* r, uint32_t addr) {
    asm volatile("ldmatrix.sync.aligned.m8n8.x4.trans.shared.b16 {%0,%1,%2,%3}, [%4];"
                 : "=r"(r[0]), "=r"(r[1]), "=r"(r[2]), "=r"(r[3]) : "r"(addr));
}

// fp16 HMMA, fp32 accumulate
__device__ __forceinline__ void mma_f16(float* d, const uint32_t* a, const uint32_t* b) {
    asm volatile("mma.sync.aligned.m16n8k16.row.col.f32.f16.f16.f32 "
                 "{%0,%1,%2,%3}, {%4,%5,%6,%7}, {%8,%9}, {%0,%1,%2,%3};"
                 : "+f"(d[0]), "+f"(d[1]), "+f"(d[2]), "+f"(d[3])
                 : "r"(a[0]), "r"(a[1]), "r"(a[2]), "r"(a[3]), "r"(b[0]), "r"(b[1]));
}

// pack two fp32 into f16x2 (lo -> low half)
__device__ __forceinline__ uint32_t pack_f16(float lo, float hi) {
    uint32_t d;
    asm("cvt.rn.f16x2.f32 %0, %1, %2;" : "=r"(d) : "f"(hi), "f"(lo));
    return d;
}
// residual pair after fp16 truncation of (lo, hi) packed in hp
__device__ __forceinline__ uint32_t resid_f16(uint32_t hp, float lo, float hi) {
    __half2 h = *reinterpret_cast<__half2*>(&hp);
    return pack_f16(lo - __half2float(__low2half(h)),
                    hi - __half2float(__high2half(h)));
}

// ---------------------------------------------------------------------------
// Split-fp16 HMMA GEMM (2-pass): C = (Ahi+Alo)[M,K] @ Whi[N,K]^T
// OUT==0: write fp32 C (+bias).  OUT==1: fp16 hi/lo.  OUT==2: fp16 hi only.
// Block 128x128, BK=32, 256 threads, 3-stage cp.async pipeline,
// XOR-swizzled smem, pass-major mma ordering.
// ---------------------------------------------------------------------------
#define GK     1024
#define BK     32
#define NITER  (GK / BK)               // 32
#define TILEB  (128 * 64)              // [128 rows][32 f16 = 64B]
#define STAGEB (3 * TILEB)             // 24 KB (Ahi, Alo, Whi)
#define NSTAGE 3
#define GEMM_SMEM (NSTAGE * STAGEB)    // 72 KB

template<int OUT>
__global__ __launch_bounds__(256, 2) void gemm_mma(
    const __half* __restrict__ Ahi, const __half* __restrict__ Alo,
    const __half* __restrict__ Whi,
    const float* __restrict__ bias, float* __restrict__ C,
    __half* __restrict__ Chi, __half* __restrict__ Clo, int N)
{
    extern __shared__ char sm[];
    const uint32_t sbase = smem_u32(sm);
    const int tid  = threadIdx.x;
    const int lane = tid & 31;
    const int warp = tid >> 5;
    const int wm = warp & 1;
    const int wn = warp >> 1;
    const int m0 = blockIdx.y * 128;
    const int n0 = blockIdx.x * 128;

    float acc[4][4][4];
    #pragma unroll
    for (int i = 0; i < 4; i++)
        #pragma unroll
        for (int j = 0; j < 4; j++)
            #pragma unroll
            for (int q = 0; q < 4; q++) acc[i][j][q] = 0.f;

    const __half* gs[3] = {Ahi, Alo, Whi};
    const int r0s[3] = {m0, m0, n0};

    auto soff = [&](int s, int t) -> uint32_t { return sbase + s * STAGEB + t * TILEB; };

    auto load_stage = [&](int s, int k0) {
        #pragma unroll
        for (int t = 0; t < 3; t++) {
            const char* gp = (const char*)(gs[t] + (size_t)r0s[t] * GK + k0);
            #pragma unroll
            for (int j = 0; j < 2; j++) {
                int id = tid + j * 256;
                int r = id >> 2, c = id & 3;
                uint32_t sw = r * 64 + ((c ^ ((r >> 1) & 3)) << 4);
                cp_async16(soff(s, t) + sw, gp + (size_t)r * (GK * 2) + c * 16);
            }
        }
        CP_COMMIT();
    };

    load_stage(0, 0);
    load_stage(1, BK);

    const int sub = lane >> 3, rin = lane & 7;
    const int a_row_off = (sub & 1) * 8 + rin;
    const int a_chunk   = sub >> 1;
    const int b_row_off = (sub >> 1) * 8 + rin;
    const int b_chunk   = sub & 1;

    for (int it = 0; it < NITER; it++) {
        const int s = it % NSTAGE;
        if (it == NITER - 1) { CP_WAIT0(); } else { CP_WAIT1(); }
        __syncthreads();

        const uint32_t aH = soff(s, 0), aL = soff(s, 1), wH = soff(s, 2);

        #pragma unroll
        for (int ks = 0; ks < 2; ks++) {
            uint32_t Ah[4][4], Al[4][4], Bh[4][2];

            #pragma unroll
            for (int mi = 0; mi < 4; mi++) {
                int row = wm * 64 + mi * 16 + a_row_off;
                int c = ks * 2 + a_chunk;
                uint32_t off = row * 64 + ((c ^ ((row >> 1) & 3)) << 4);
                ldsm_x4(Ah[mi], aH + off);
                ldsm_x4(Al[mi], aL + off);
            }
            #pragma unroll
            for (int p = 0; p < 2; p++) {
                int row = wn * 32 + p * 16 + b_row_off;
                int c = ks * 2 + b_chunk;
                uint32_t off = row * 64 + ((c ^ ((row >> 1) & 3)) << 4);
                uint32_t t0[4];
                ldsm_x4(t0, wH + off);
                Bh[p*2  ][0] = t0[0]; Bh[p*2  ][1] = t0[1];
                Bh[p*2+1][0] = t0[2]; Bh[p*2+1][1] = t0[3];
            }

            #pragma unroll
            for (int mi = 0; mi < 4; mi++)
                #pragma unroll
                for (int ni = 0; ni < 4; ni++)
                    mma_f16(acc[mi][ni], Ah[mi], Bh[ni]);   // hi*hi
            #pragma unroll
            for (int mi = 0; mi < 4; mi++)
                #pragma unroll
                for (int ni = 0; ni < 4; ni++)
                    mma_f16(acc[mi][ni], Al[mi], Bh[ni]);   // lo*hi
        }
        if (it + 2 < NITER) load_stage((it + 2) % NSTAGE, (it + 2) * BK);
    }

    const int g = lane >> 2, c2 = (lane & 3) * 2;
    #pragma unroll
    for (int mi = 0; mi < 4; mi++) {
        int row = m0 + wm * 64 + mi * 16 + g;
        #pragma unroll
        for (int ni = 0; ni < 4; ni++) {
            int col = n0 + wn * 32 + ni * 8 + c2;
            if (OUT == 0) {
                float b0 = 0.f, b1 = 0.f;
                if (bias) { b0 = bias[col]; b1 = bias[col + 1]; }
                float2 v0 = make_float2(acc[mi][ni][0] + b0, acc[mi][ni][1] + b1);
                float2 v1 = make_float2(acc[mi][ni][2] + b0, acc[mi][ni][3] + b1);
                *(float2*)&C[(size_t)row * N + col] = v0;
                *(float2*)&C[(size_t)(row + 8) * N + col] = v1;
            } else {
                uint32_t hp0 = pack_f16(acc[mi][ni][0], acc[mi][ni][1]);
                uint32_t hp1 = pack_f16(acc[mi][ni][2], acc[mi][ni][3]);
                *(uint32_t*)&Chi[(size_t)row * N + col] = hp0;
                *(uint32_t*)&Chi[(size_t)(row + 8) * N + col] = hp1;
                if (OUT == 1) {
                    uint32_t lp0 = resid_f16(hp0, acc[mi][ni][0], acc[mi][ni][1]);
                    uint32_t lp1 = resid_f16(hp1, acc[mi][ni][2], acc[mi][ni][3]);
                    *(uint32_t*)&Clo[(size_t)row * N + col] = lp0;
                    *(uint32_t*)&Clo[(size_t)(row + 8) * N + col] = lp1;
                }
            }
        }
    }
}

// ---------------------------------------------------------------------------
// fp32 -> fp16 hi/lo split (elementwise, float4)
// ---------------------------------------------------------------------------
__global__ __launch_bounds__(256) void split_kernel(
    const float* __restrict__ in, __half* __restrict__ hi,
    __half* __restrict__ lo, int n4)
{
    int i = blockIdx.x * blockDim.x + threadIdx.x;
    if (i >= n4) return;
    float4 v = ((const float4*)in)[i];
    __half h[4], l[4];
    float f[4] = {v.x, v.y, v.z, v.w};
    #pragma unroll
    for (int j = 0; j < 4; j++) {
        h[j] = __float2half_rn(f[j]);
        l[j] = __float2half_rn(f[j] - __half2float(h[j]));
    }
    ((ushort4*)hi)[i] = make_ushort4(__half_as_ushort(h[0]), __half_as_ushort(h[1]),
                                     __half_as_ushort(h[2]), __half_as_ushort(h[3]));
    ((ushort4*)lo)[i] = make_ushort4(__half_as_ushort(l[0]), __half_as_ushort(l[1]),
                                     __half_as_ushort(l[2]), __half_as_ushort(l[3]));
}

// ---------------------------------------------------------------------------
// fp32 [K][N] -> transposed fp16 hi (+ optional lo) [N][K]
// ---------------------------------------------------------------------------
__global__ __launch_bounds__(256) void splitT_kernel(
    const float* __restrict__ w, __half* __restrict__ thi,
    __half* __restrict__ tlo, int K, int N)
{
    __shared__ float t[32][33];
    const int n0 = blockIdx.x * 32, k0 = blockIdx.y * 32;
    const int tx = threadIdx.x & 31, ty = threadIdx.x >> 5;
    #pragma unroll
    for (int j = ty; j < 32; j += 8)
        t[j][tx] = w[(size_t)(k0 + j) * N + n0 + tx];
    __syncthreads();
    #pragma unroll
    for (int j = ty; j < 32; j += 8) {
        float v = t[tx][j];
        __half h = __float2half_rn(v);
        thi[(size_t)(n0 + j) * K + k0 + tx] = h;
        if (tlo) {
            __half l = __float2half_rn(v - __half2float(h));
            tlo[(size_t)(n0 + j) * K + k0 + tx] = l;
        }
    }
}

// ---------------------------------------------------------------------------
// HMMA flash attention, fp16.
// S = Qh Kh^T (1-pass; logit error ~8e-5, crushed by SCALE).
// O += (Ph + Pl) Vh   (P split 2-pass; V_lo dropped, error ~2.4e-4).
// Only qkv_hi read. smem: Qh 16KB + 2 stages x (Kh 8KB + Vh 8KB) = 48KB.
// ---------------------------------------------------------------------------
#define AT_Q    0
#define AT_ST   16384
#define AT_STB  16384
#define AT_KH   0
#define AT_VH   8192
#define AT_SMEM (AT_ST + 2 * AT_STB)   // 49152

__global__ __launch_bounds__(256, 1) void attn_mma(
    const __half* __restrict__ qh,
    __half* __restrict__ ohi, __half* __restrict__ olo)
{
    extern __shared__ char sm[];
    const uint32_t sb = smem_u32(sm);
    const int tid  = threadIdx.x;
    const int lane = tid & 31;
    const int warp = tid >> 5;
    const int sub = lane >> 3, rin = lane & 7;
    const int g = lane >> 2, t = lane & 3;

    const int qt = blockIdx.x, head = blockIdx.y, batch = blockIdx.z;
    const size_t tok0 = (size_t)batch * SEQ;
    const size_t qbase = (tok0 + qt * 128) * QKVDIM + head * HDIM;

    // Q tile (hi only): 128 rows x 8 chunks = 1024 cps
    #pragma unroll
    for (int j = 0; j < 4; j++) {
        int id = tid + j * 256;
        int r = id >> 3, c = id & 7;
        uint32_t sw = r * 128 + ((c ^ (r & 7)) << 4);
        cp_async16(sb + AT_Q + sw, (const char*)(qh + qbase) + (size_t)r * QKVDIM * 2 + c * 16);
    }
    CP_COMMIT();

    auto load_kv = [&](int s, int jt) {
        size_t kb = (tok0 + jt * 64) * QKVDIM + DIM + head * HDIM;
        size_t vb = kb + DIM;
        uint32_t st = sb + AT_ST + s * AT_STB;
        #pragma unroll
        for (int j = 0; j < 2; j++) {
            int id = tid + j * 256;
            int r = id >> 3, c = id & 7;
            uint32_t sw = r * 128 + ((c ^ (r & 7)) << 4);
            size_t go = (size_t)r * QKVDIM * 2 + c * 16;
            cp_async16(st + AT_KH + sw, (const char*)(qh + kb) + go);
            cp_async16(st + AT_VH + sw, (const char*)(qh + vb) + go);
        }
        CP_COMMIT();
    };

    load_kv(0, 0);
    load_kv(1, 1);

    CP_WAIT2();
    __syncthreads();
    uint32_t Qh[4][4];
    {
        int row = warp * 16 + (sub & 1) * 8 + rin;
        #pragma unroll
        for (int s4 = 0; s4 < 4; s4++) {
            int ch = 2 * s4 + (sub >> 1);
            uint32_t off = row * 128 + ((ch ^ (row & 7)) << 4);
            ldsm_x4(Qh[s4], sb + AT_Q + off);
        }
    }

    float m0 = -1e30f, m1 = -1e30f, l0 = 0.f, l1 = 0.f;
    float O[8][4];
    #pragma unroll
    for (int b = 0; b < 8; b++)
        #pragma unroll
        for (int q = 0; q < 4; q++) O[b][q] = 0.f;

    for (int jt = 0; jt < SEQ / 64; jt++) {
        const int s = jt & 1;
        if (jt == SEQ / 64 - 1) { CP_WAIT0(); } else { CP_WAIT1(); }
        __syncthreads();
        const uint32_t stb = sb + AT_ST + s * AT_STB;

        // ---- S = Qh Kh^T (1-pass) ----
        float S[8][4];
        #pragma unroll
        for (int b = 0; b < 8; b++)
            #pragma unroll
            for (int q = 0; q < 4; q++) S[b][q] = 0.f;

        #pragma unroll
        for (int s4 = 0; s4 < 4; s4++) {
            int bch = 2 * s4 + (sub & 1);
            #pragma unroll
            for (int jp = 0; jp < 4; jp++) {
                int row = jp * 16 + (sub >> 1) * 8 + rin;
                uint32_t off = row * 128 + ((bch ^ (row & 7)) << 4);
                uint32_t kh[4];
                ldsm_x4(kh, stb + AT_KH + off);
                mma_f16(S[2*jp],   Qh[s4], kh);
                mma_f16(S[2*jp+1], Qh[s4], kh + 2);
            }
        }

        // ---- online softmax ----
        float mx0 = -1e30f, mx1 = -1e30f;
        #pragma unroll
        for (int b = 0; b < 8; b++) {
            #pragma unroll
            for (int q = 0; q < 4; q++) S[b][q] *= SCALE;
            mx0 = fmaxf(mx0, fmaxf(S[b][0], S[b][1]));
            mx1 = fmaxf(mx1, fmaxf(S[b][2], S[b][3]));
        }
        #pragma unroll
        for (int off = 1; off < 4; off <<= 1) {
            mx0 = fmaxf(mx0, __shfl_xor_sync(0xffffffffu, mx0, off));
            mx1 = fmaxf(mx1, __shfl_xor_sync(0xffffffffu, mx1, off));
        }
        float mn0 = fmaxf(m0, mx0), mn1 = fmaxf(m1, mx1);
        float al0 = __expf(m0 - mn0), al1 = __expf(m1 - mn1);
        m0 = mn0; m1 = mn1;

        float rs0 = 0.f, rs1 = 0.f;
        #pragma unroll
        for (int b = 0; b < 8; b++) {
            S[b][0] = __expf(S[b][0] - mn0); rs0 += S[b][0];
            S[b][1] = __expf(S[b][1] - mn0); rs0 += S[b][1];
            S[b][2] = __expf(S[b][2] - mn1); rs1 += S[b][2];
            S[b][3] = __expf(S[b][3] - mn1); rs1 += S[b][3];
        }
        #pragma unroll
        for (int off = 1; off < 4; off <<= 1) {
            rs0 += __shfl_xor_sync(0xffffffffu, rs0, off);
            rs1 += __shfl_xor_sync(0xffffffffu, rs1, off);
        }
        l0 = l0 * al0 + rs0;
        l1 = l1 * al1 + rs1;
        #pragma unroll
        for (int b = 0; b < 8; b++) {
            O[b][0] *= al0; O[b][1] *= al0;
            O[b][2] *= al1; O[b][3] *= al1;
        }

        // ---- O += (Ph + Pl) Vh ----
        #pragma unroll
        for (int a = 0; a < 4; a++) {
            uint32_t Ph[4], Pl[4];
            Ph[0] = pack_f16(S[2*a][0],   S[2*a][1]);
            Ph[1] = pack_f16(S[2*a][2],   S[2*a][3]);
            Ph[2] = pack_f16(S[2*a+1][0], S[2*a+1][1]);
            Ph[3] = pack_f16(S[2*a+1][2], S[2*a+1][3]);
            Pl[0] = resid_f16(Ph[0], S[2*a][0],   S[2*a][1]);
            Pl[1] = resid_f16(Ph[1], S[2*a][2],   S[2*a][3]);
            Pl[2] = resid_f16(Ph[2], S[2*a+1][0], S[2*a+1][1]);
            Pl[3] = resid_f16(Ph[3], S[2*a+1][2], S[2*a+1][3]);

            int vrow = a * 16 + (sub & 1) * 8 + rin;
            #pragma unroll
            for (int bp = 0; bp < 4; bp++) {
                int ch = 2 * bp + (sub >> 1);
                uint32_t off = vrow * 128 + ((ch ^ (vrow & 7)) << 4);
                uint32_t vh[4];
                ldsm_x4_t(vh, stb + AT_VH + off);
                mma_f16(O[2*bp],   Ph, vh);
                mma_f16(O[2*bp],   Pl, vh);
                mma_f16(O[2*bp+1], Ph, vh + 2);
                mma_f16(O[2*bp+1], Pl, vh + 2);
            }
        }
        __syncthreads();
        if (jt + 2 < SEQ / 64) load_kv(s, jt + 2);
    }

    // ---- epilogue: write fp16 hi/lo of O / l ----
    float inv0 = 1.f / l0, inv1 = 1.f / l1;
    size_t t0 = tok0 + qt * 128 + warp * 16 + g;
    size_t t1 = t0 + 8;
    #pragma unroll
    for (int b = 0; b < 8; b++) {
        int col = head * HDIM + b * 8 + 2 * t;
        float o00 = O[b][0] * inv0, o01 = O[b][1] * inv0;
        float o10 = O[b][2] * inv1, o11 = O[b][3] * inv1;
        uint32_t hp0 = pack_f16(o00, o01);
        uint32_t hp1 = pack_f16(o10, o11);
        *(uint32_t*)&ohi[t0 * DIM + col] = hp0;
        *(uint32_t*)&ohi[t1 * DIM + col] = hp1;
        *(uint32_t*)&olo[t0 * DIM + col] = resid_f16(hp0, o00, o01);
        *(uint32_t*)&olo[t1 * DIM + col] = resid_f16(hp1, o10, o11);
    }
}

// ----------------------------------------------------------------------------
// Launch
// ----------------------------------------------------------------------------
extern "C" void kernel_launch(void* const* d_in, const int* in_sizes, int n_in,
                              void* d_out, int out_size)
{
    const float* x     = (const float*)d_in[0];
    const float* w_qkv = (const float*)d_in[1];
    const float* w_out = (const float*)d_in[2];
    const float* b_out = (const float*)d_in[3];
    float* out = (float*)d_out;

    void *p_xhi, *p_xlo, *p_w1hi, *p_w2hi, *p_w2lo, *p_qh, *p_ahi, *p_alo;
    cudaGetSymbolAddress(&p_xhi, g_xhi);
    cudaGetSymbolAddress(&p_xlo, g_xlo);
    cudaGetSymbolAddress(&p_w1hi, g_w1hi);
    cudaGetSymbolAddress(&p_w2hi, g_w2hi);
    cudaGetSymbolAddress(&p_w2lo, g_w2lo);
    cudaGetSymbolAddress(&p_qh, g_qkvhi);
    cudaGetSymbolAddress(&p_ahi, g_ahi);
    cudaGetSymbolAddress(&p_alo, g_alo);

    cudaFuncSetAttribute(gemm_mma<0>, cudaFuncAttributeMaxDynamicSharedMemorySize, GEMM_SMEM);
    cudaFuncSetAttribute(gemm_mma<2>, cudaFuncAttributeMaxDynamicSharedMemorySize, GEMM_SMEM);
    cudaFuncSetAttribute(attn_mma,    cudaFuncAttributeMaxDynamicSharedMemorySize, AT_SMEM);

    // 0) splits: x -> hi+lo; w_qkv^T -> hi only; w_out^T -> hi+lo
    split_kernel<<<(TOKENS * DIM / 4 + 255) / 256, 256>>>(
        x, (__half*)p_xhi, (__half*)p_xlo, TOKENS * DIM / 4);
    splitT_kernel<<<dim3(QKVDIM / 32, DIM / 32), 256>>>(
        w_qkv, (__half*)p_w1hi, nullptr, DIM, QKVDIM);
    splitT_kernel<<<dim3(DIM / 32, DIM / 32), 256>>>(
        w_out, (__half*)p_w2hi, (__half*)p_w2lo, DIM, DIM);

    // 1) qkv = x @ w_qkv -> fp16 hi only (2-pass)          [8192, 3072]
    gemm_mma<2><<<dim3(QKVDIM / 128, TOKENS / 128), 256, GEMM_SMEM>>>(
        (const __half*)p_xhi, (const __half*)p_xlo,
        (const __half*)p_w1hi,
        nullptr, nullptr,
        (__half*)p_qh, nullptr, QKVDIM);

    // 2) attention -> fp16 hi/lo                            [8192, 1024]
    attn_mma<<<dim3(SEQ / 128, HEADS, BATCH), 256, AT_SMEM>>>(
        (const __half*)p_qh, (__half*)p_ahi, (__half*)p_alo);

    // 3) out = attn @ w_out + b (2-pass)                    [8192, 1024]
    gemm_mma<0><<<dim3(DIM / 128, TOKENS / 128), 256, GEMM_SMEM>>>(
        (const __half*)p_ahi, (const __half*)p_alo,
        (const __half*)p_w2hi,
        b_out, out, nullptr, nullptr, DIM);
}

// round 10
// speedup vs baseline: 2.0007x; 1.1930x over previous
#include <cuda_runtime.h>
#include <cuda_fp16.h>
#include <cstdint>

// Problem constants
#define BATCH  8
#define SEQ    1024
#define DIM    1024
#define HEADS  16
#define HDIM   64
#define TOKENS (BATCH * SEQ)          // 8192
#define QKVDIM (3 * DIM)              // 3072
#define SCALE  0.03125f               // 1024^-0.5

// ---------------------------------------------------------------------------
// Scratch (device globals: allocation-guard safe)
// ---------------------------------------------------------------------------
__device__ __half g_xhi[(size_t)TOKENS * DIM];
__device__ __half g_xlo[(size_t)TOKENS * DIM];
__device__ __half g_w1hi[(size_t)QKVDIM * DIM];      // w_qkv^T [3072][1024]
__device__ __half g_w2hi[(size_t)DIM * DIM];         // w_out^T [1024][1024]
__device__ __half g_w2lo[(size_t)DIM * DIM];
__device__ __half g_qkvhi[(size_t)TOKENS * QKVDIM];  // qkv hi [8192][3072]
__device__ __half g_ahi[(size_t)TOKENS * DIM];
__device__ __half g_alo[(size_t)TOKENS * DIM];

// ---------------------------------------------------------------------------
// Helpers
// ---------------------------------------------------------------------------
__device__ __forceinline__ uint32_t smem_u32(const void* p) {
    uint32_t a;
    asm("{ .reg .u64 t; cvta.to.shared.u64 t, %1; cvt.u32.u64 %0, t; }" : "=r"(a) : "l"(p));
    return a;
}

__device__ __forceinline__ void cp_async16(uint32_t dst, const void* src) {
    asm volatile("cp.async.cg.shared.global [%0], [%1], 16;\n" :: "r"(dst), "l"(src));
}
#define CP_COMMIT() asm volatile("cp.async.commit_group;\n" ::: "memory")
#define CP_WAIT2()  asm volatile("cp.async.wait_group 2;\n" ::: "memory")
#define CP_WAIT1()  asm volatile("cp.async.wait_group 1;\n" ::: "memory")
#define CP_WAIT0()  asm volatile("cp.async.wait_group 0;\n" ::: "memory")

__device__ __forceinline__ void ldsm_x4(uint32_t* r, uint32_t addr) {
    asm volatile("ldmatrix.sync.aligned.m8n8.x4.shared.b16 {%0,%1,%2,%3}, [%4];"
                 : "=r"(r[0]), "=r"(r[1]), "=r"(r[2]), "=r"(r[3]) : "r"(addr));
}

__device__ __forceinline__ void ldsm_x4_t(uint32_t* r, uint32_t addr) {
    asm volatile("ldmatrix.sync.aligned.m8n8.x4.trans.shared.b16 {%0,%1,%2,%3}, [%4];"
                 : "=r"(r[0]), "=r"(r[1]), "=r"(r[2]), "=r"(r[3]) : "r"(addr));
}

// fp16 HMMA, fp32 accumulate
__device__ __forceinline__ void mma_f16(float* d, const uint32_t* a, const uint32_t* b) {
    asm volatile("mma.sync.aligned.m16n8k16.row.col.f32.f16.f16.f32 "
                 "{%0,%1,%2,%3}, {%4,%5,%6,%7}, {%8,%9}, {%0,%1,%2,%3};"
                 : "+f"(d[0]), "+f"(d[1]), "+f"(d[2]), "+f"(d[3])
                 : "r"(a[0]), "r"(a[1]), "r"(a[2]), "r"(a[3]), "r"(b[0]), "r"(b[1]));
}

// pack two fp32 into f16x2 (lo -> low half)
__device__ __forceinline__ uint32_t pack_f16(float lo, float hi) {
    uint32_t d;
    asm("cvt.rn.f16x2.f32 %0, %1, %2;" : "=r"(d) : "f"(hi), "f"(lo));
    return d;
}
// residual pair after fp16 truncation of (lo, hi) packed in hp
__device__ __forceinline__ uint32_t resid_f16(uint32_t hp, float lo, float hi) {
    __half2 h = *reinterpret_cast<__half2*>(&hp);
    return pack_f16(lo - __half2float(__low2half(h)),
                    hi - __half2float(__high2half(h)));
}

// ---------------------------------------------------------------------------
// Split-fp16 HMMA GEMM: C = (Ahi [+ Alo if n0>=lo_start])[M,K] @ Whi[N,K]^T
// OUT==0: write fp32 C (+bias).  OUT==1: fp16 hi/lo.  OUT==2: fp16 hi only.
// lo_start: N-offset where the Alo (2nd) pass begins. 0 = always, N = never.
// Block 128x128, BK=32, 256 threads, 3-stage cp.async pipeline,
// XOR-swizzled smem, pass-major mma ordering.
// ---------------------------------------------------------------------------
#define GK     1024
#define BK     32
#define NITER  (GK / BK)               // 32
#define TILEB  (128 * 64)              // [128 rows][32 f16 = 64B]
#define STAGEB (3 * TILEB)             // 24 KB (Ahi, Alo, Whi)
#define NSTAGE 3
#define GEMM_SMEM (NSTAGE * STAGEB)    // 72 KB

template<int OUT>
__global__ __launch_bounds__(256, 2) void gemm_mma(
    const __half* __restrict__ Ahi, const __half* __restrict__ Alo,
    const __half* __restrict__ Whi,
    const float* __restrict__ bias, float* __restrict__ C,
    __half* __restrict__ Chi, __half* __restrict__ Clo, int N, int lo_start)
{
    extern __shared__ char sm[];
    const uint32_t sbase = smem_u32(sm);
    const int tid  = threadIdx.x;
    const int lane = tid & 31;
    const int warp = tid >> 5;
    const int wm = warp & 1;
    const int wn = warp >> 1;
    const int m0 = blockIdx.y * 128;
    const int n0 = blockIdx.x * 128;
    const bool use_lo = (n0 >= lo_start);   // block-uniform

    float acc[4][4][4];
    #pragma unroll
    for (int i = 0; i < 4; i++)
        #pragma unroll
        for (int j = 0; j < 4; j++)
            #pragma unroll
            for (int q = 0; q < 4; q++) acc[i][j][q] = 0.f;

    auto soff = [&](int s, int t) -> uint32_t { return sbase + s * STAGEB + t * TILEB; };

    auto load_stage = [&](int s, int k0) {
        // Ahi tile
        {
            const char* gp = (const char*)(Ahi + (size_t)m0 * GK + k0);
            #pragma unroll
            for (int j = 0; j < 2; j++) {
                int id = tid + j * 256;
                int r = id >> 2, c = id & 3;
                uint32_t sw = r * 64 + ((c ^ ((r >> 1) & 3)) << 4);
                cp_async16(soff(s, 0) + sw, gp + (size_t)r * (GK * 2) + c * 16);
            }
        }
        // Alo tile (only in split region)
        if (use_lo) {
            const char* gp = (const char*)(Alo + (size_t)m0 * GK + k0);
            #pragma unroll
            for (int j = 0; j < 2; j++) {
                int id = tid + j * 256;
                int r = id >> 2, c = id & 3;
                uint32_t sw = r * 64 + ((c ^ ((r >> 1) & 3)) << 4);
                cp_async16(soff(s, 1) + sw, gp + (size_t)r * (GK * 2) + c * 16);
            }
        }
        // Whi tile
        {
            const char* gp = (const char*)(Whi + (size_t)n0 * GK + k0);
            #pragma unroll
            for (int j = 0; j < 2; j++) {
                int id = tid + j * 256;
                int r = id >> 2, c = id & 3;
                uint32_t sw = r * 64 + ((c ^ ((r >> 1) & 3)) << 4);
                cp_async16(soff(s, 2) + sw, gp + (size_t)r * (GK * 2) + c * 16);
            }
        }
        CP_COMMIT();
    };

    load_stage(0, 0);
    load_stage(1, BK);

    const int sub = lane >> 3, rin = lane & 7;
    const int a_row_off = (sub & 1) * 8 + rin;
    const int a_chunk   = sub >> 1;
    const int b_row_off = (sub >> 1) * 8 + rin;
    const int b_chunk   = sub & 1;

    for (int it = 0; it < NITER; it++) {
        const int s = it % NSTAGE;
        if (it == NITER - 1) { CP_WAIT0(); } else { CP_WAIT1(); }
        __syncthreads();

        const uint32_t aH = soff(s, 0), aL = soff(s, 1), wH = soff(s, 2);

        #pragma unroll
        for (int ks = 0; ks < 2; ks++) {
            uint32_t Ah[4][4], Bh[4][2];

            #pragma unroll
            for (int mi = 0; mi < 4; mi++) {
                int row = wm * 64 + mi * 16 + a_row_off;
                int c = ks * 2 + a_chunk;
                uint32_t off = row * 64 + ((c ^ ((row >> 1) & 3)) << 4);
                ldsm_x4(Ah[mi], aH + off);
            }
            #pragma unroll
            for (int p = 0; p < 2; p++) {
                int row = wn * 32 + p * 16 + b_row_off;
                int c = ks * 2 + b_chunk;
                uint32_t off = row * 64 + ((c ^ ((row >> 1) & 3)) << 4);
                uint32_t t0[4];
                ldsm_x4(t0, wH + off);
                Bh[p*2  ][0] = t0[0]; Bh[p*2  ][1] = t0[1];
                Bh[p*2+1][0] = t0[2]; Bh[p*2+1][1] = t0[3];
            }

            #pragma unroll
            for (int mi = 0; mi < 4; mi++)
                #pragma unroll
                for (int ni = 0; ni < 4; ni++)
                    mma_f16(acc[mi][ni], Ah[mi], Bh[ni]);   // hi*hi

            if (use_lo) {
                uint32_t Al[4][4];
                #pragma unroll
                for (int mi = 0; mi < 4; mi++) {
                    int row = wm * 64 + mi * 16 + a_row_off;
                    int c = ks * 2 + a_chunk;
                    uint32_t off = row * 64 + ((c ^ ((row >> 1) & 3)) << 4);
                    ldsm_x4(Al[mi], aL + off);
                }
                #pragma unroll
                for (int mi = 0; mi < 4; mi++)
                    #pragma unroll
                    for (int ni = 0; ni < 4; ni++)
                        mma_f16(acc[mi][ni], Al[mi], Bh[ni]);   // lo*hi
            }
        }
        if (it + 2 < NITER) load_stage((it + 2) % NSTAGE, (it + 2) * BK);
    }

    const int g = lane >> 2, c2 = (lane & 3) * 2;
    #pragma unroll
    for (int mi = 0; mi < 4; mi++) {
        int row = m0 + wm * 64 + mi * 16 + g;
        #pragma unroll
        for (int ni = 0; ni < 4; ni++) {
            int col = n0 + wn * 32 + ni * 8 + c2;
            if (OUT == 0) {
                float b0 = 0.f, b1 = 0.f;
                if (bias) { b0 = bias[col]; b1 = bias[col + 1]; }
                float2 v0 = make_float2(acc[mi][ni][0] + b0, acc[mi][ni][1] + b1);
                float2 v1 = make_float2(acc[mi][ni][2] + b0, acc[mi][ni][3] + b1);
                *(float2*)&C[(size_t)row * N + col] = v0;
                *(float2*)&C[(size_t)(row + 8) * N + col] = v1;
            } else {
                uint32_t hp0 = pack_f16(acc[mi][ni][0], acc[mi][ni][1]);
                uint32_t hp1 = pack_f16(acc[mi][ni][2], acc[mi][ni][3]);
                *(uint32_t*)&Chi[(size_t)row * N + col] = hp0;
                *(uint32_t*)&Chi[(size_t)(row + 8) * N + col] = hp1;
                if (OUT == 1) {
                    uint32_t lp0 = resid_f16(hp0, acc[mi][ni][0], acc[mi][ni][1]);
                    uint32_t lp1 = resid_f16(hp1, acc[mi][ni][2], acc[mi][ni][3]);
                    *(uint32_t*)&Clo[(size_t)row * N + col] = lp0;
                    *(uint32_t*)&Clo[(size_t)(row + 8) * N + col] = lp1;
                }
            }
        }
    }
}

// ---------------------------------------------------------------------------
// fp32 -> fp16 hi/lo split (elementwise, float4)
// ---------------------------------------------------------------------------
__global__ __launch_bounds__(256) void split_kernel(
    const float* __restrict__ in, __half* __restrict__ hi,
    __half* __restrict__ lo, int n4)
{
    int i = blockIdx.x * blockDim.x + threadIdx.x;
    if (i >= n4) return;
    float4 v = ((const float4*)in)[i];
    __half h[4], l[4];
    float f[4] = {v.x, v.y, v.z, v.w};
    #pragma unroll
    for (int j = 0; j < 4; j++) {
        h[j] = __float2half_rn(f[j]);
        l[j] = __float2half_rn(f[j] - __half2float(h[j]));
    }
    ((ushort4*)hi)[i] = make_ushort4(__half_as_ushort(h[0]), __half_as_ushort(h[1]),
                                     __half_as_ushort(h[2]), __half_as_ushort(h[3]));
    ((ushort4*)lo)[i] = make_ushort4(__half_as_ushort(l[0]), __half_as_ushort(l[1]),
                                     __half_as_ushort(l[2]), __half_as_ushort(l[3]));
}

// ---------------------------------------------------------------------------
// fp32 [K][N] -> transposed fp16 hi (+ optional lo) [N][K]
// ---------------------------------------------------------------------------
__global__ __launch_bounds__(256) void splitT_kernel(
    const float* __restrict__ w, __half* __restrict__ thi,
    __half* __restrict__ tlo, int K, int N)
{
    __shared__ float t[32][33];
    const int n0 = blockIdx.x * 32, k0 = blockIdx.y * 32;
    const int tx = threadIdx.x & 31, ty = threadIdx.x >> 5;
    #pragma unroll
    for (int j = ty; j < 32; j += 8)
        t[j][tx] = w[(size_t)(k0 + j) * N + n0 + tx];
    __syncthreads();
    #pragma unroll
    for (int j = ty; j < 32; j += 8) {
        float v = t[tx][j];
        __half h = __float2half_rn(v);
        thi[(size_t)(n0 + j) * K + k0 + tx] = h;
        if (tlo) {
            __half l = __float2half_rn(v - __half2float(h));
            tlo[(size_t)(n0 + j) * K + k0 + tx] = l;
        }
    }
}

// ---------------------------------------------------------------------------
// HMMA flash attention, fp16 (unchanged from Round 9 — known-good).
// S = Qh Kh^T (1-pass); O += (Ph + Pl) Vh.
// ---------------------------------------------------------------------------
#define AT_Q    0
#define AT_ST   16384
#define AT_STB  16384
#define AT_KH   0
#define AT_VH   8192
#define AT_SMEM (AT_ST + 2 * AT_STB)   // 49152

__global__ __launch_bounds__(256, 1) void attn_mma(
    const __half* __restrict__ qh,
    __half* __restrict__ ohi, __half* __restrict__ olo)
{
    extern __shared__ char sm[];
    const uint32_t sb = smem_u32(sm);
    const int tid  = threadIdx.x;
    const int lane = tid & 31;
    const int warp = tid >> 5;
    const int sub = lane >> 3, rin = lane & 7;
    const int g = lane >> 2, t = lane & 3;

    const int qt = blockIdx.x, head = blockIdx.y, batch = blockIdx.z;
    const size_t tok0 = (size_t)batch * SEQ;
    const size_t qbase = (tok0 + qt * 128) * QKVDIM + head * HDIM;

    #pragma unroll
    for (int j = 0; j < 4; j++) {
        int id = tid + j * 256;
        int r = id >> 3, c = id & 7;
        uint32_t sw = r * 128 + ((c ^ (r & 7)) << 4);
        cp_async16(sb + AT_Q + sw, (const char*)(qh + qbase) + (size_t)r * QKVDIM * 2 + c * 16);
    }
    CP_COMMIT();

    auto load_kv = [&](int s, int jt) {
        size_t kb = (tok0 + jt * 64) * QKVDIM + DIM + head * HDIM;
        size_t vb = kb + DIM;
        uint32_t st = sb + AT_ST + s * AT_STB;
        #pragma unroll
        for (int j = 0; j < 2; j++) {
            int id = tid + j * 256;
            int r = id >> 3, c = id & 7;
            uint32_t sw = r * 128 + ((c ^ (r & 7)) << 4);
            size_t go = (size_t)r * QKVDIM * 2 + c * 16;
            cp_async16(st + AT_KH + sw, (const char*)(qh + kb) + go);
            cp_async16(st + AT_VH + sw, (const char*)(qh + vb) + go);
        }
        CP_COMMIT();
    };

    load_kv(0, 0);
    load_kv(1, 1);

    CP_WAIT2();
    __syncthreads();
    uint32_t Qh[4][4];
    {
        int row = warp * 16 + (sub & 1) * 8 + rin;
        #pragma unroll
        for (int s4 = 0; s4 < 4; s4++) {
            int ch = 2 * s4 + (sub >> 1);
            uint32_t off = row * 128 + ((ch ^ (row & 7)) << 4);
            ldsm_x4(Qh[s4], sb + AT_Q + off);
        }
    }

    float m0 = -1e30f, m1 = -1e30f, l0 = 0.f, l1 = 0.f;
    float O[8][4];
    #pragma unroll
    for (int b = 0; b < 8; b++)
        #pragma unroll
        for (int q = 0; q < 4; q++) O[b][q] = 0.f;

    for (int jt = 0; jt < SEQ / 64; jt++) {
        const int s = jt & 1;
        if (jt == SEQ / 64 - 1) { CP_WAIT0(); } else { CP_WAIT1(); }
        __syncthreads();
        const uint32_t stb = sb + AT_ST + s * AT_STB;

        float S[8][4];
        #pragma unroll
        for (int b = 0; b < 8; b++)
            #pragma unroll
            for (int q = 0; q < 4; q++) S[b][q] = 0.f;

        #pragma unroll
        for (int s4 = 0; s4 < 4; s4++) {
            int bch = 2 * s4 + (sub & 1);
            #pragma unroll
            for (int jp = 0; jp < 4; jp++) {
                int row = jp * 16 + (sub >> 1) * 8 + rin;
                uint32_t off = row * 128 + ((bch ^ (row & 7)) << 4);
                uint32_t kh[4];
                ldsm_x4(kh, stb + AT_KH + off);
                mma_f16(S[2*jp],   Qh[s4], kh);
                mma_f16(S[2*jp+1], Qh[s4], kh + 2);
            }
        }

        float mx0 = -1e30f, mx1 = -1e30f;
        #pragma unroll
        for (int b = 0; b < 8; b++) {
            #pragma unroll
            for (int q = 0; q < 4; q++) S[b][q] *= SCALE;
            mx0 = fmaxf(mx0, fmaxf(S[b][0], S[b][1]));
            mx1 = fmaxf(mx1, fmaxf(S[b][2], S[b][3]));
        }
        #pragma unroll
        for (int off = 1; off < 4; off <<= 1) {
            mx0 = fmaxf(mx0, __shfl_xor_sync(0xffffffffu, mx0, off));
            mx1 = fmaxf(mx1, __shfl_xor_sync(0xffffffffu, mx1, off));
        }
        float mn0 = fmaxf(m0, mx0), mn1 = fmaxf(m1, mx1);
        float al0 = __expf(m0 - mn0), al1 = __expf(m1 - mn1);
        m0 = mn0; m1 = mn1;

        float rs0 = 0.f, rs1 = 0.f;
        #pragma unroll
        for (int b = 0; b < 8; b++) {
            S[b][0] = __expf(S[b][0] - mn0); rs0 += S[b][0];
            S[b][1] = __expf(S[b][1] - mn0); rs0 += S[b][1];
            S[b][2] = __expf(S[b][2] - mn1); rs1 += S[b][2];
            S[b][3] = __expf(S[b][3] - mn1); rs1 += S[b][3];
        }
        #pragma unroll
        for (int off = 1; off < 4; off <<= 1) {
            rs0 += __shfl_xor_sync(0xffffffffu, rs0, off);
            rs1 += __shfl_xor_sync(0xffffffffu, rs1, off);
        }
        l0 = l0 * al0 + rs0;
        l1 = l1 * al1 + rs1;
        #pragma unroll
        for (int b = 0; b < 8; b++) {
            O[b][0] *= al0; O[b][1] *= al0;
            O[b][2] *= al1; O[b][3] *= al1;
        }

        #pragma unroll
        for (int a = 0; a < 4; a++) {
            uint32_t Ph[4], Pl[4];
            Ph[0] = pack_f16(S[2*a][0],   S[2*a][1]);
            Ph[1] = pack_f16(S[2*a][2],   S[2*a][3]);
            Ph[2] = pack_f16(S[2*a+1][0], S[2*a+1][1]);
            Ph[3] = pack_f16(S[2*a+1][2], S[2*a+1][3]);
            Pl[0] = resid_f16(Ph[0], S[2*a][0],   S[2*a][1]);
            Pl[1] = resid_f16(Ph[1], S[2*a][2],   S[2*a][3]);
            Pl[2] = resid_f16(Ph[2], S[2*a+1][0], S[2*a+1][1]);
            Pl[3] = resid_f16(Ph[3], S[2*a+1][2], S[2*a+1][3]);

            int vrow = a * 16 + (sub & 1) * 8 + rin;
            #pragma unroll
            for (int bp = 0; bp < 4; bp++) {
                int ch = 2 * bp + (sub >> 1);
                uint32_t off = vrow * 128 + ((ch ^ (vrow & 7)) << 4);
                uint32_t vh[4];
                ldsm_x4_t(vh, stb + AT_VH + off);
                mma_f16(O[2*bp],   Ph, vh);
                mma_f16(O[2*bp],   Pl, vh);
                mma_f16(O[2*bp+1], Ph, vh + 2);
                mma_f16(O[2*bp+1], Pl, vh + 2);
            }
        }
        __syncthreads();
        if (jt + 2 < SEQ / 64) load_kv(s, jt + 2);
    }

    float inv0 = 1.f / l0, inv1 = 1.f / l1;
    size_t t0 = tok0 + qt * 128 + warp * 16 + g;
    size_t t1 = t0 + 8;
    #pragma unroll
    for (int b = 0; b < 8; b++) {
        int col = head * HDIM + b * 8 + 2 * t;
        float o00 = O[b][0] * inv0, o01 = O[b][1] * inv0;
        float o10 = O[b][2] * inv1, o11 = O[b][3] * inv1;
        uint32_t hp0 = pack_f16(o00, o01);
        uint32_t hp1 = pack_f16(o10, o11);
        *(uint32_t*)&ohi[t0 * DIM + col] = hp0;
        *(uint32_t*)&ohi[t1 * DIM + col] = hp1;
        *(uint32_t*)&olo[t0 * DIM + col] = resid_f16(hp0, o00, o01);
        *(uint32_t*)&olo[t1 * DIM + col] = resid_f16(hp1, o10, o11);
    }
}

// ----------------------------------------------------------------------------
// Launch
// ----------------------------------------------------------------------------
extern "C" void kernel_launch(void* const* d_in, const int* in_sizes, int n_in,
                              void* d_out, int out_size)
{
    const float* x     = (const float*)d_in[0];
    const float* w_qkv = (const float*)d_in[1];
    const float* w_out = (const float*)d_in[2];
    const float* b_out = (const float*)d_in[3];
    float* out = (float*)d_out;

    void *p_xhi, *p_xlo, *p_w1hi, *p_w2hi, *p_w2lo, *p_qh, *p_ahi, *p_alo;
    cudaGetSymbolAddress(&p_xhi, g_xhi);
    cudaGetSymbolAddress(&p_xlo, g_xlo);
    cudaGetSymbolAddress(&p_w1hi, g_w1hi);
    cudaGetSymbolAddress(&p_w2hi, g_w2hi);
    cudaGetSymbolAddress(&p_w2lo, g_w2lo);
    cudaGetSymbolAddress(&p_qh, g_qkvhi);
    cudaGetSymbolAddress(&p_ahi, g_ahi);
    cudaGetSymbolAddress(&p_alo, g_alo);

    cudaFuncSetAttribute(gemm_mma<0>, cudaFuncAttributeMaxDynamicSharedMemorySize, GEMM_SMEM);
    cudaFuncSetAttribute(gemm_mma<2>, cudaFuncAttributeMaxDynamicSharedMemorySize, GEMM_SMEM);
    cudaFuncSetAttribute(attn_mma,    cudaFuncAttributeMaxDynamicSharedMemorySize, AT_SMEM);

    // 0) splits: x -> hi+lo; w_qkv^T -> hi only; w_out^T -> hi only
    split_kernel<<<(TOKENS * DIM / 4 + 255) / 256, 256>>>(
        x, (__half*)p_xhi, (__half*)p_xlo, TOKENS * DIM / 4);
    splitT_kernel<<<dim3(QKVDIM / 32, DIM / 32), 256>>>(
        w_qkv, (__half*)p_w1hi, nullptr, DIM, QKVDIM);
    splitT_kernel<<<dim3(DIM / 32, DIM / 32), 256>>>(
        w_out, (__half*)p_w2hi, (__half*)p_w2lo, DIM, DIM);

    // 1) qkv = x @ w_qkv -> fp16 hi only.
    //    Q,K columns (n<2048): 1-pass pure fp16 (softmax-insensitive).
    //    V columns (n>=2048): 2-pass x-split.
    gemm_mma<2><<<dim3(QKVDIM / 128, TOKENS / 128), 256, GEMM_SMEM>>>(
        (const __half*)p_xhi, (const __half*)p_xlo,
        (const __half*)p_w1hi,
        nullptr, nullptr,
        (__half*)p_qh, nullptr, QKVDIM, /*lo_start=*/2 * DIM);

    // 2) attention -> fp16 hi/lo                            [8192, 1024]
    attn_mma<<<dim3(SEQ / 128, HEADS, BATCH), 256, AT_SMEM>>>(
        (const __half*)p_qh, (__half*)p_ahi, (__half*)p_alo);

    // 3) out = attn @ w_out + b (2-pass everywhere)         [8192, 1024]
    gemm_mma<0><<<dim3(DIM / 128, TOKENS / 128), 256, GEMM_SMEM>>>(
        (const __half*)p_ahi, (const __half*)p_alo,
        (const __half*)p_w2hi,
        b_out, out, nullptr, nullptr, DIM, /*lo_start=*/0);
}

// round 11
// speedup vs baseline: 2.3184x; 1.1588x over previous
#include <cuda_runtime.h>
#include <cuda_fp16.h>
#include <cstdint>

// Problem constants
#define BATCH  8
#define SEQ    1024
#define DIM    1024
#define HEADS  16
#define HDIM   64
#define TOKENS (BATCH * SEQ)          // 8192
#define QKVDIM (3 * DIM)              // 3072
#define SCALE  0.03125f               // 1024^-0.5

// ---------------------------------------------------------------------------
// Scratch (device globals: allocation-guard safe)
// ---------------------------------------------------------------------------
__device__ __half g_xhi[(size_t)TOKENS * DIM];
__device__ __half g_xlo[(size_t)TOKENS * DIM];
__device__ __half g_w1hi[(size_t)QKVDIM * DIM];      // w_qkv^T [3072][1024]
__device__ __half g_w2hi[(size_t)DIM * DIM];         // w_out^T [1024][1024]
__device__ __half g_qkvhi[(size_t)TOKENS * QKVDIM];  // qkv hi [8192][3072]
__device__ __half g_ahi[(size_t)TOKENS * DIM];

// ---------------------------------------------------------------------------
// Helpers
// ---------------------------------------------------------------------------
__device__ __forceinline__ uint32_t smem_u32(const void* p) {
    uint32_t a;
    asm("{ .reg .u64 t; cvta.to.shared.u64 t, %1; cvt.u32.u64 %0, t; }" : "=r"(a) : "l"(p));
    return a;
}

__device__ __forceinline__ void cp_async16(uint32_t dst, const void* src) {
    asm volatile("cp.async.cg.shared.global [%0], [%1], 16;\n" :: "r"(dst), "l"(src));
}
#define CP_COMMIT() asm volatile("cp.async.commit_group;\n" ::: "memory")
#define CP_WAIT2()  asm volatile("cp.async.wait_group 2;\n" ::: "memory")
#define CP_WAIT1()  asm volatile("cp.async.wait_group 1;\n" ::: "memory")
#define CP_WAIT0()  asm volatile("cp.async.wait_group 0;\n" ::: "memory")

__device__ __forceinline__ void ldsm_x4(uint32_t* r, uint32_t addr) {
    asm volatile("ldmatrix.sync.aligned.m8n8.x4.shared.b16 {%0,%1,%2,%3}, [%4];"
                 : "=r"(r[0]), "=r"(r[1]), "=r"(r[2]), "=r"(r[3]) : "r"(addr));
}

__device__ __forceinline__ void ldsm_x4_t(uint32_t* r, uint32_t addr) {
    asm volatile("ldmatrix.sync.aligned.m8n8.x4.trans.shared.b16 {%0,%1,%2,%3}, [%4];"
                 : "=r"(r[0]), "=r"(r[1]), "=r"(r[2]), "=r"(r[3]) : "r"(addr));
}

// fp16 HMMA, fp32 accumulate
__device__ __forceinline__ void mma_f16(float* d, const uint32_t* a, const uint32_t* b) {
    asm volatile("mma.sync.aligned.m16n8k16.row.col.f32.f16.f16.f32 "
                 "{%0,%1,%2,%3}, {%4,%5,%6,%7}, {%8,%9}, {%0,%1,%2,%3};"
                 : "+f"(d[0]), "+f"(d[1]), "+f"(d[2]), "+f"(d[3])
                 : "r"(a[0]), "r"(a[1]), "r"(a[2]), "r"(a[3]), "r"(b[0]), "r"(b[1]));
}

// pack two fp32 into f16x2 (lo -> low half)
__device__ __forceinline__ uint32_t pack_f16(float lo, float hi) {
    uint32_t d;
    asm("cvt.rn.f16x2.f32 %0, %1, %2;" : "=r"(d) : "f"(hi), "f"(lo));
    return d;
}
// residual pair after fp16 truncation of (lo, hi) packed in hp
__device__ __forceinline__ uint32_t resid_f16(uint32_t hp, float lo, float hi) {
    __half2 h = *reinterpret_cast<__half2*>(&hp);
    return pack_f16(lo - __half2float(__low2half(h)),
                    hi - __half2float(__high2half(h)));
}

// ---------------------------------------------------------------------------
// Split-fp16 HMMA GEMM: C = (Ahi [+ Alo if n0>=lo_start])[M,K] @ Whi[N,K]^T
// OUT==0: write fp32 C (+bias).  OUT==2: fp16 hi only.
// lo_start: N-offset where the Alo (2nd) pass begins. 0 = always, N = never.
// Block 128x128, BK=32, 256 threads, 3-stage cp.async pipeline,
// XOR-swizzled smem, pass-major mma ordering.
// ---------------------------------------------------------------------------
#define GK     1024
#define BK     32
#define NITER  (GK / BK)               // 32
#define TILEB  (128 * 64)              // [128 rows][32 f16 = 64B]
#define STAGEB (3 * TILEB)             // 24 KB (Ahi, Alo, Whi)
#define NSTAGE 3
#define GEMM_SMEM (NSTAGE * STAGEB)    // 72 KB

template<int OUT>
__global__ __launch_bounds__(256, 2) void gemm_mma(
    const __half* __restrict__ Ahi, const __half* __restrict__ Alo,
    const __half* __restrict__ Whi,
    const float* __restrict__ bias, float* __restrict__ C,
    __half* __restrict__ Chi, int N, int lo_start)
{
    extern __shared__ char sm[];
    const uint32_t sbase = smem_u32(sm);
    const int tid  = threadIdx.x;
    const int lane = tid & 31;
    const int warp = tid >> 5;
    const int wm = warp & 1;
    const int wn = warp >> 1;
    const int m0 = blockIdx.y * 128;
    const int n0 = blockIdx.x * 128;
    const bool use_lo = (n0 >= lo_start);   // block-uniform

    float acc[4][4][4];
    #pragma unroll
    for (int i = 0; i < 4; i++)
        #pragma unroll
        for (int j = 0; j < 4; j++)
            #pragma unroll
            for (int q = 0; q < 4; q++) acc[i][j][q] = 0.f;

    auto soff = [&](int s, int t) -> uint32_t { return sbase + s * STAGEB + t * TILEB; };

    auto load_stage = [&](int s, int k0) {
        {
            const char* gp = (const char*)(Ahi + (size_t)m0 * GK + k0);
            #pragma unroll
            for (int j = 0; j < 2; j++) {
                int id = tid + j * 256;
                int r = id >> 2, c = id & 3;
                uint32_t sw = r * 64 + ((c ^ ((r >> 1) & 3)) << 4);
                cp_async16(soff(s, 0) + sw, gp + (size_t)r * (GK * 2) + c * 16);
            }
        }
        if (use_lo) {
            const char* gp = (const char*)(Alo + (size_t)m0 * GK + k0);
            #pragma unroll
            for (int j = 0; j < 2; j++) {
                int id = tid + j * 256;
                int r = id >> 2, c = id & 3;
                uint32_t sw = r * 64 + ((c ^ ((r >> 1) & 3)) << 4);
                cp_async16(soff(s, 1) + sw, gp + (size_t)r * (GK * 2) + c * 16);
            }
        }
        {
            const char* gp = (const char*)(Whi + (size_t)n0 * GK + k0);
            #pragma unroll
            for (int j = 0; j < 2; j++) {
                int id = tid + j * 256;
                int r = id >> 2, c = id & 3;
                uint32_t sw = r * 64 + ((c ^ ((r >> 1) & 3)) << 4);
                cp_async16(soff(s, 2) + sw, gp + (size_t)r * (GK * 2) + c * 16);
            }
        }
        CP_COMMIT();
    };

    load_stage(0, 0);
    load_stage(1, BK);

    const int sub = lane >> 3, rin = lane & 7;
    const int a_row_off = (sub & 1) * 8 + rin;
    const int a_chunk   = sub >> 1;
    const int b_row_off = (sub >> 1) * 8 + rin;
    const int b_chunk   = sub & 1;

    for (int it = 0; it < NITER; it++) {
        const int s = it % NSTAGE;
        if (it == NITER - 1) { CP_WAIT0(); } else { CP_WAIT1(); }
        __syncthreads();

        const uint32_t aH = soff(s, 0), aL = soff(s, 1), wH = soff(s, 2);

        #pragma unroll
        for (int ks = 0; ks < 2; ks++) {
            uint32_t Ah[4][4], Bh[4][2];

            #pragma unroll
            for (int mi = 0; mi < 4; mi++) {
                int row = wm * 64 + mi * 16 + a_row_off;
                int c = ks * 2 + a_chunk;
                uint32_t off = row * 64 + ((c ^ ((row >> 1) & 3)) << 4);
                ldsm_x4(Ah[mi], aH + off);
            }
            #pragma unroll
            for (int p = 0; p < 2; p++) {
                int row = wn * 32 + p * 16 + b_row_off;
                int c = ks * 2 + b_chunk;
                uint32_t off = row * 64 + ((c ^ ((row >> 1) & 3)) << 4);
                uint32_t t0[4];
                ldsm_x4(t0, wH + off);
                Bh[p*2  ][0] = t0[0]; Bh[p*2  ][1] = t0[1];
                Bh[p*2+1][0] = t0[2]; Bh[p*2+1][1] = t0[3];
            }

            #pragma unroll
            for (int mi = 0; mi < 4; mi++)
                #pragma unroll
                for (int ni = 0; ni < 4; ni++)
                    mma_f16(acc[mi][ni], Ah[mi], Bh[ni]);   // hi*hi

            if (use_lo) {
                uint32_t Al[4][4];
                #pragma unroll
                for (int mi = 0; mi < 4; mi++) {
                    int row = wm * 64 + mi * 16 + a_row_off;
                    int c = ks * 2 + a_chunk;
                    uint32_t off = row * 64 + ((c ^ ((row >> 1) & 3)) << 4);
                    ldsm_x4(Al[mi], aL + off);
                }
                #pragma unroll
                for (int mi = 0; mi < 4; mi++)
                    #pragma unroll
                    for (int ni = 0; ni < 4; ni++)
                        mma_f16(acc[mi][ni], Al[mi], Bh[ni]);   // lo*hi
            }
        }
        if (it + 2 < NITER) load_stage((it + 2) % NSTAGE, (it + 2) * BK);
    }

    const int g = lane >> 2, c2 = (lane & 3) * 2;
    #pragma unroll
    for (int mi = 0; mi < 4; mi++) {
        int row = m0 + wm * 64 + mi * 16 + g;
        #pragma unroll
        for (int ni = 0; ni < 4; ni++) {
            int col = n0 + wn * 32 + ni * 8 + c2;
            if (OUT == 0) {
                float b0 = 0.f, b1 = 0.f;
                if (bias) { b0 = bias[col]; b1 = bias[col + 1]; }
                float2 v0 = make_float2(acc[mi][ni][0] + b0, acc[mi][ni][1] + b1);
                float2 v1 = make_float2(acc[mi][ni][2] + b0, acc[mi][ni][3] + b1);
                *(float2*)&C[(size_t)row * N + col] = v0;
                *(float2*)&C[(size_t)(row + 8) * N + col] = v1;
            } else {
                uint32_t hp0 = pack_f16(acc[mi][ni][0], acc[mi][ni][1]);
                uint32_t hp1 = pack_f16(acc[mi][ni][2], acc[mi][ni][3]);
                *(uint32_t*)&Chi[(size_t)row * N + col] = hp0;
                *(uint32_t*)&Chi[(size_t)(row + 8) * N + col] = hp1;
            }
        }
    }
}

// ---------------------------------------------------------------------------
// fp32 -> fp16 hi/lo split (elementwise, float4)
// ---------------------------------------------------------------------------
__global__ __launch_bounds__(256) void split_kernel(
    const float* __restrict__ in, __half* __restrict__ hi,
    __half* __restrict__ lo, int n4)
{
    int i = blockIdx.x * blockDim.x + threadIdx.x;
    if (i >= n4) return;
    float4 v = ((const float4*)in)[i];
    __half h[4], l[4];
    float f[4] = {v.x, v.y, v.z, v.w};
    #pragma unroll
    for (int j = 0; j < 4; j++) {
        h[j] = __float2half_rn(f[j]);
        l[j] = __float2half_rn(f[j] - __half2float(h[j]));
    }
    ((ushort4*)hi)[i] = make_ushort4(__half_as_ushort(h[0]), __half_as_ushort(h[1]),
                                     __half_as_ushort(h[2]), __half_as_ushort(h[3]));
    ((ushort4*)lo)[i] = make_ushort4(__half_as_ushort(l[0]), __half_as_ushort(l[1]),
                                     __half_as_ushort(l[2]), __half_as_ushort(l[3]));
}

// ---------------------------------------------------------------------------
// fp32 [K][N] -> transposed fp16 hi [N][K]
// ---------------------------------------------------------------------------
__global__ __launch_bounds__(256) void splitT_kernel(
    const float* __restrict__ w, __half* __restrict__ thi, int K, int N)
{
    __shared__ float t[32][33];
    const int n0 = blockIdx.x * 32, k0 = blockIdx.y * 32;
    const int tx = threadIdx.x & 31, ty = threadIdx.x >> 5;
    #pragma unroll
    for (int j = ty; j < 32; j += 8)
        t[j][tx] = w[(size_t)(k0 + j) * N + n0 + tx];
    __syncthreads();
    #pragma unroll
    for (int j = ty; j < 32; j += 8)
        thi[(size_t)(n0 + j) * K + k0 + tx] = __float2half_rn(t[tx][j]);
}

// ---------------------------------------------------------------------------
// HMMA flash attention, fp16.
// S = Qh Kh^T (1-pass); O += (Ph + Pl) Vh. Output: fp16 hi only.
// 2 CTAs/SM (regs capped 112, smem 48KB each).
// ---------------------------------------------------------------------------
#define AT_Q    0
#define AT_ST   16384
#define AT_STB  16384
#define AT_KH   0
#define AT_VH   8192
#define AT_SMEM (AT_ST + 2 * AT_STB)   // 49152

__global__ __launch_bounds__(256, 2) void attn_mma(
    const __half* __restrict__ qh, __half* __restrict__ ohi)
{
    extern __shared__ char sm[];
    const uint32_t sb = smem_u32(sm);
    const int tid  = threadIdx.x;
    const int lane = tid & 31;
    const int warp = tid >> 5;
    const int sub = lane >> 3, rin = lane & 7;
    const int g = lane >> 2, t = lane & 3;

    const int qt = blockIdx.x, head = blockIdx.y, batch = blockIdx.z;
    const size_t tok0 = (size_t)batch * SEQ;
    const size_t qbase = (tok0 + qt * 128) * QKVDIM + head * HDIM;

    #pragma unroll
    for (int j = 0; j < 4; j++) {
        int id = tid + j * 256;
        int r = id >> 3, c = id & 7;
        uint32_t sw = r * 128 + ((c ^ (r & 7)) << 4);
        cp_async16(sb + AT_Q + sw, (const char*)(qh + qbase) + (size_t)r * QKVDIM * 2 + c * 16);
    }
    CP_COMMIT();

    auto load_kv = [&](int s, int jt) {
        size_t kb = (tok0 + jt * 64) * QKVDIM + DIM + head * HDIM;
        size_t vb = kb + DIM;
        uint32_t st = sb + AT_ST + s * AT_STB;
        #pragma unroll
        for (int j = 0; j < 2; j++) {
            int id = tid + j * 256;
            int r = id >> 3, c = id & 7;
            uint32_t sw = r * 128 + ((c ^ (r & 7)) << 4);
            size_t go = (size_t)r * QKVDIM * 2 + c * 16;
            cp_async16(st + AT_KH + sw, (const char*)(qh + kb) + go);
            cp_async16(st + AT_VH + sw, (const char*)(qh + vb) + go);
        }
        CP_COMMIT();
    };

    load_kv(0, 0);
    load_kv(1, 1);

    CP_WAIT2();
    __syncthreads();
    uint32_t Qh[4][4];
    {
        int row = warp * 16 + (sub & 1) * 8 + rin;
        #pragma unroll
        for (int s4 = 0; s4 < 4; s4++) {
            int ch = 2 * s4 + (sub >> 1);
            uint32_t off = row * 128 + ((ch ^ (row & 7)) << 4);
            ldsm_x4(Qh[s4], sb + AT_Q + off);
        }
    }

    float m0 = -1e30f, m1 = -1e30f, l0 = 0.f, l1 = 0.f;
    float O[8][4];
    #pragma unroll
    for (int b = 0; b < 8; b++)
        #pragma unroll
        for (int q = 0; q < 4; q++) O[b][q] = 0.f;

    for (int jt = 0; jt < SEQ / 64; jt++) {
        const int s = jt & 1;
        if (jt == SEQ / 64 - 1) { CP_WAIT0(); } else { CP_WAIT1(); }
        __syncthreads();
        const uint32_t stb = sb + AT_ST + s * AT_STB;

        float S[8][4];
        #pragma unroll
        for (int b = 0; b < 8; b++)
            #pragma unroll
            for (int q = 0; q < 4; q++) S[b][q] = 0.f;

        #pragma unroll
        for (int s4 = 0; s4 < 4; s4++) {
            int bch = 2 * s4 + (sub & 1);
            #pragma unroll
            for (int jp = 0; jp < 4; jp++) {
                int row = jp * 16 + (sub >> 1) * 8 + rin;
                uint32_t off = row * 128 + ((bch ^ (row & 7)) << 4);
                uint32_t kh[4];
                ldsm_x4(kh, stb + AT_KH + off);
                mma_f16(S[2*jp],   Qh[s4], kh);
                mma_f16(S[2*jp+1], Qh[s4], kh + 2);
            }
        }

        float mx0 = -1e30f, mx1 = -1e30f;
        #pragma unroll
        for (int b = 0; b < 8; b++) {
            #pragma unroll
            for (int q = 0; q < 4; q++) S[b][q] *= SCALE;
            mx0 = fmaxf(mx0, fmaxf(S[b][0], S[b][1]));
            mx1 = fmaxf(mx1, fmaxf(S[b][2], S[b][3]));
        }
        #pragma unroll
        for (int off = 1; off < 4; off <<= 1) {
            mx0 = fmaxf(mx0, __shfl_xor_sync(0xffffffffu, mx0, off));
            mx1 = fmaxf(mx1, __shfl_xor_sync(0xffffffffu, mx1, off));
        }
        float mn0 = fmaxf(m0, mx0), mn1 = fmaxf(m1, mx1);
        float al0 = __expf(m0 - mn0), al1 = __expf(m1 - mn1);
        m0 = mn0; m1 = mn1;

        float rs0 = 0.f, rs1 = 0.f;
        #pragma unroll
        for (int b = 0; b < 8; b++) {
            S[b][0] = __expf(S[b][0] - mn0); rs0 += S[b][0];
            S[b][1] = __expf(S[b][1] - mn0); rs0 += S[b][1];
            S[b][2] = __expf(S[b][2] - mn1); rs1 += S[b][2];
            S[b][3] = __expf(S[b][3] - mn1); rs1 += S[b][3];
        }
        #pragma unroll
        for (int off = 1; off < 4; off <<= 1) {
            rs0 += __shfl_xor_sync(0xffffffffu, rs0, off);
            rs1 += __shfl_xor_sync(0xffffffffu, rs1, off);
        }
        l0 = l0 * al0 + rs0;
        l1 = l1 * al1 + rs1;
        #pragma unroll
        for (int b = 0; b < 8; b++) {
            O[b][0] *= al0; O[b][1] *= al0;
            O[b][2] *= al1; O[b][3] *= al1;
        }

        #pragma unroll
        for (int a = 0; a < 4; a++) {
            uint32_t Ph[4], Pl[4];
            Ph[0] = pack_f16(S[2*a][0],   S[2*a][1]);
            Ph[1] = pack_f16(S[2*a][2],   S[2*a][3]);
            Ph[2] = pack_f16(S[2*a+1][0], S[2*a+1][1]);
            Ph[3] = pack_f16(S[2*a+1][2], S[2*a+1][3]);
            Pl[0] = resid_f16(Ph[0], S[2*a][0],   S[2*a][1]);
            Pl[1] = resid_f16(Ph[1], S[2*a][2],   S[2*a][3]);
            Pl[2] = resid_f16(Ph[2], S[2*a+1][0], S[2*a+1][1]);
            Pl[3] = resid_f16(Ph[3], S[2*a+1][2], S[2*a+1][3]);

            int vrow = a * 16 + (sub & 1) * 8 + rin;
            #pragma unroll
            for (int bp = 0; bp < 4; bp++) {
                int ch = 2 * bp + (sub >> 1);
                uint32_t off = vrow * 128 + ((ch ^ (vrow & 7)) << 4);
                uint32_t vh[4];
                ldsm_x4_t(vh, stb + AT_VH + off);
                mma_f16(O[2*bp],   Ph, vh);
                mma_f16(O[2*bp],   Pl, vh);
                mma_f16(O[2*bp+1], Ph, vh + 2);
                mma_f16(O[2*bp+1], Pl, vh + 2);
            }
        }
        __syncthreads();
        if (jt + 2 < SEQ / 64) load_kv(s, jt + 2);
    }

    // epilogue: fp16 hi only
    float inv0 = 1.f / l0, inv1 = 1.f / l1;
    size_t t0 = tok0 + qt * 128 + warp * 16 + g;
    size_t t1 = t0 + 8;
    #pragma unroll
    for (int b = 0; b < 8; b++) {
        int col = head * HDIM + b * 8 + 2 * t;
        *(uint32_t*)&ohi[t0 * DIM + col] = pack_f16(O[b][0] * inv0, O[b][1] * inv0);
        *(uint32_t*)&ohi[t1 * DIM + col] = pack_f16(O[b][2] * inv1, O[b][3] * inv1);
    }
}

// ----------------------------------------------------------------------------
// Launch
// ----------------------------------------------------------------------------
extern "C" void kernel_launch(void* const* d_in, const int* in_sizes, int n_in,
                              void* d_out, int out_size)
{
    const float* x     = (const float*)d_in[0];
    const float* w_qkv = (const float*)d_in[1];
    const float* w_out = (const float*)d_in[2];
    const float* b_out = (const float*)d_in[3];
    float* out = (float*)d_out;

    void *p_xhi, *p_xlo, *p_w1hi, *p_w2hi, *p_qh, *p_ahi;
    cudaGetSymbolAddress(&p_xhi, g_xhi);
    cudaGetSymbolAddress(&p_xlo, g_xlo);
    cudaGetSymbolAddress(&p_w1hi, g_w1hi);
    cudaGetSymbolAddress(&p_w2hi, g_w2hi);
    cudaGetSymbolAddress(&p_qh, g_qkvhi);
    cudaGetSymbolAddress(&p_ahi, g_ahi);

    cudaFuncSetAttribute(gemm_mma<0>, cudaFuncAttributeMaxDynamicSharedMemorySize, GEMM_SMEM);
    cudaFuncSetAttribute(gemm_mma<2>, cudaFuncAttributeMaxDynamicSharedMemorySize, GEMM_SMEM);
    cudaFuncSetAttribute(attn_mma,    cudaFuncAttributeMaxDynamicSharedMemorySize, AT_SMEM);

    // 0) splits: x -> hi+lo; w_qkv^T -> hi; w_out^T -> hi
    split_kernel<<<(TOKENS * DIM / 4 + 255) / 256, 256>>>(
        x, (__half*)p_xhi, (__half*)p_xlo, TOKENS * DIM / 4);
    splitT_kernel<<<dim3(QKVDIM / 32, DIM / 32), 256>>>(
        w_qkv, (__half*)p_w1hi, DIM, QKVDIM);
    splitT_kernel<<<dim3(DIM / 32, DIM / 32), 256>>>(
        w_out, (__half*)p_w2hi, DIM, DIM);

    // 1) qkv = x @ w_qkv -> fp16 hi only.
    //    Q,K columns (n<2048): 1-pass; V columns (n>=2048): 2-pass x-split.
    gemm_mma<2><<<dim3(QKVDIM / 128, TOKENS / 128), 256, GEMM_SMEM>>>(
        (const __half*)p_xhi, (const __half*)p_xlo,
        (const __half*)p_w1hi,
        nullptr, nullptr,
        (__half*)p_qh, QKVDIM, /*lo_start=*/2 * DIM);

    // 2) attention -> fp16 hi only                          [8192, 1024]
    attn_mma<<<dim3(SEQ / 128, HEADS, BATCH), 256, AT_SMEM>>>(
        (const __half*)p_qh, (__half*)p_ahi);

    // 3) out = attn @ w_out + b (pure 1-pass fp16)          [8192, 1024]
    gemm_mma<0><<<dim3(DIM / 128, TOKENS / 128), 256, GEMM_SMEM>>>(
        (const __half*)p_ahi, nullptr,
        (const __half*)p_w2hi,
        b_out, out, nullptr, DIM, /*lo_start=*/DIM);
}

// round 12
// speedup vs baseline: 2.4056x; 1.0376x over previous
#include <cuda_runtime.h>
#include <cuda_fp16.h>
#include <cstdint>

// Problem constants
#define BATCH  8
#define SEQ    1024
#define DIM    1024
#define HEADS  16
#define HDIM   64
#define TOKENS (BATCH * SEQ)          // 8192
#define QKVDIM (3 * DIM)              // 3072
#define SCALE  0.03125f               // 1024^-0.5

// ---------------------------------------------------------------------------
// Scratch (device globals: allocation-guard safe)
// ---------------------------------------------------------------------------
__device__ __half g_xhi[(size_t)TOKENS * DIM];
__device__ __half g_w1hi[(size_t)QKVDIM * DIM];      // w_qkv^T [3072][1024]
__device__ __half g_w2hi[(size_t)DIM * DIM];         // w_out^T [1024][1024]
__device__ __half g_qkvhi[(size_t)TOKENS * QKVDIM];  // qkv hi [8192][3072]
__device__ __half g_ahi[(size_t)TOKENS * DIM];

// ---------------------------------------------------------------------------
// Helpers
// ---------------------------------------------------------------------------
__device__ __forceinline__ uint32_t smem_u32(const void* p) {
    uint32_t a;
    asm("{ .reg .u64 t; cvta.to.shared.u64 t, %1; cvt.u32.u64 %0, t; }" : "=r"(a) : "l"(p));
    return a;
}

__device__ __forceinline__ void cp_async16(uint32_t dst, const void* src) {
    asm volatile("cp.async.cg.shared.global [%0], [%1], 16;\n" :: "r"(dst), "l"(src));
}
#define CP_COMMIT() asm volatile("cp.async.commit_group;\n" ::: "memory")
#define CP_WAIT2()  asm volatile("cp.async.wait_group 2;\n" ::: "memory")
#define CP_WAIT1()  asm volatile("cp.async.wait_group 1;\n" ::: "memory")
#define CP_WAIT0()  asm volatile("cp.async.wait_group 0;\n" ::: "memory")

__device__ __forceinline__ void ldsm_x4(uint32_t* r, uint32_t addr) {
    asm volatile("ldmatrix.sync.aligned.m8n8.x4.shared.b16 {%0,%1,%2,%3}, [%4];"
                 : "=r"(r[0]), "=r"(r[1]), "=r"(r[2]), "=r"(r[3]) : "r"(addr));
}

__device__ __forceinline__ void ldsm_x4_t(uint32_t* r, uint32_t addr) {
    asm volatile("ldmatrix.sync.aligned.m8n8.x4.trans.shared.b16 {%0,%1,%2,%3}, [%4];"
                 : "=r"(r[0]), "=r"(r[1]), "=r"(r[2]), "=r"(r[3]) : "r"(addr));
}

// fp16 HMMA, fp32 accumulate
__device__ __forceinline__ void mma_f16(float* d, const uint32_t* a, const uint32_t* b) {
    asm volatile("mma.sync.aligned.m16n8k16.row.col.f32.f16.f16.f32 "
                 "{%0,%1,%2,%3}, {%4,%5,%6,%7}, {%8,%9}, {%0,%1,%2,%3};"
                 : "+f"(d[0]), "+f"(d[1]), "+f"(d[2]), "+f"(d[3])
                 : "r"(a[0]), "r"(a[1]), "r"(a[2]), "r"(a[3]), "r"(b[0]), "r"(b[1]));
}

// pack two fp32 into f16x2 (lo -> low half)
__device__ __forceinline__ uint32_t pack_f16(float lo, float hi) {
    uint32_t d;
    asm("cvt.rn.f16x2.f32 %0, %1, %2;" : "=r"(d) : "f"(hi), "f"(lo));
    return d;
}
// residual pair after fp16 truncation of (lo, hi) packed in hp
__device__ __forceinline__ uint32_t resid_f16(uint32_t hp, float lo, float hi) {
    __half2 h = *reinterpret_cast<__half2*>(&hp);
    return pack_f16(lo - __half2float(__low2half(h)),
                    hi - __half2float(__high2half(h)));
}

// ---------------------------------------------------------------------------
// Pure fp16 HMMA GEMM (1-pass): C = Ahi[M,K] @ Whi[N,K]^T
// OUT==0: write fp32 C (+bias).  OUT==2: fp16 hi only.
// Block 128x128, BK=32, 256 threads, 3-stage cp.async pipeline,
// XOR-swizzled smem.
// ---------------------------------------------------------------------------
#define GK     1024
#define BK     32
#define NITER  (GK / BK)               // 32
#define TILEB  (128 * 64)              // [128 rows][32 f16 = 64B]
#define STAGEB (2 * TILEB)             // 16 KB (Ahi, Whi)
#define NSTAGE 3
#define GEMM_SMEM (NSTAGE * STAGEB)    // 48 KB

template<int OUT>
__global__ __launch_bounds__(256, 2) void gemm_mma(
    const __half* __restrict__ Ahi,
    const __half* __restrict__ Whi,
    const float* __restrict__ bias, float* __restrict__ C,
    __half* __restrict__ Chi, int N)
{
    extern __shared__ char sm[];
    const uint32_t sbase = smem_u32(sm);
    const int tid  = threadIdx.x;
    const int lane = tid & 31;
    const int warp = tid >> 5;
    const int wm = warp & 1;
    const int wn = warp >> 1;
    const int m0 = blockIdx.y * 128;
    const int n0 = blockIdx.x * 128;

    float acc[4][4][4];
    #pragma unroll
    for (int i = 0; i < 4; i++)
        #pragma unroll
        for (int j = 0; j < 4; j++)
            #pragma unroll
            for (int q = 0; q < 4; q++) acc[i][j][q] = 0.f;

    auto soff = [&](int s, int t) -> uint32_t { return sbase + s * STAGEB + t * TILEB; };

    auto load_stage = [&](int s, int k0) {
        {
            const char* gp = (const char*)(Ahi + (size_t)m0 * GK + k0);
            #pragma unroll
            for (int j = 0; j < 2; j++) {
                int id = tid + j * 256;
                int r = id >> 2, c = id & 3;
                uint32_t sw = r * 64 + ((c ^ ((r >> 1) & 3)) << 4);
                cp_async16(soff(s, 0) + sw, gp + (size_t)r * (GK * 2) + c * 16);
            }
        }
        {
            const char* gp = (const char*)(Whi + (size_t)n0 * GK + k0);
            #pragma unroll
            for (int j = 0; j < 2; j++) {
                int id = tid + j * 256;
                int r = id >> 2, c = id & 3;
                uint32_t sw = r * 64 + ((c ^ ((r >> 1) & 3)) << 4);
                cp_async16(soff(s, 1) + sw, gp + (size_t)r * (GK * 2) + c * 16);
            }
        }
        CP_COMMIT();
    };

    load_stage(0, 0);
    load_stage(1, BK);

    const int sub = lane >> 3, rin = lane & 7;
    const int a_row_off = (sub & 1) * 8 + rin;
    const int a_chunk   = sub >> 1;
    const int b_row_off = (sub >> 1) * 8 + rin;
    const int b_chunk   = sub & 1;

    for (int it = 0; it < NITER; it++) {
        const int s = it % NSTAGE;
        if (it == NITER - 1) { CP_WAIT0(); } else { CP_WAIT1(); }
        __syncthreads();

        const uint32_t aH = soff(s, 0), wH = soff(s, 1);

        #pragma unroll
        for (int ks = 0; ks < 2; ks++) {
            uint32_t Ah[4][4], Bh[4][2];

            #pragma unroll
            for (int mi = 0; mi < 4; mi++) {
                int row = wm * 64 + mi * 16 + a_row_off;
                int c = ks * 2 + a_chunk;
                uint32_t off = row * 64 + ((c ^ ((row >> 1) & 3)) << 4);
                ldsm_x4(Ah[mi], aH + off);
            }
            #pragma unroll
            for (int p = 0; p < 2; p++) {
                int row = wn * 32 + p * 16 + b_row_off;
                int c = ks * 2 + b_chunk;
                uint32_t off = row * 64 + ((c ^ ((row >> 1) & 3)) << 4);
                uint32_t t0[4];
                ldsm_x4(t0, wH + off);
                Bh[p*2  ][0] = t0[0]; Bh[p*2  ][1] = t0[1];
                Bh[p*2+1][0] = t0[2]; Bh[p*2+1][1] = t0[3];
            }

            #pragma unroll
            for (int mi = 0; mi < 4; mi++)
                #pragma unroll
                for (int ni = 0; ni < 4; ni++)
                    mma_f16(acc[mi][ni], Ah[mi], Bh[ni]);
        }
        if (it + 2 < NITER) load_stage((it + 2) % NSTAGE, (it + 2) * BK);
    }

    const int g = lane >> 2, c2 = (lane & 3) * 2;
    #pragma unroll
    for (int mi = 0; mi < 4; mi++) {
        int row = m0 + wm * 64 + mi * 16 + g;
        #pragma unroll
        for (int ni = 0; ni < 4; ni++) {
            int col = n0 + wn * 32 + ni * 8 + c2;
            if (OUT == 0) {
                float b0 = 0.f, b1 = 0.f;
                if (bias) { b0 = bias[col]; b1 = bias[col + 1]; }
                float2 v0 = make_float2(acc[mi][ni][0] + b0, acc[mi][ni][1] + b1);
                float2 v1 = make_float2(acc[mi][ni][2] + b0, acc[mi][ni][3] + b1);
                *(float2*)&C[(size_t)row * N + col] = v0;
                *(float2*)&C[(size_t)(row + 8) * N + col] = v1;
            } else {
                *(uint32_t*)&Chi[(size_t)row * N + col] =
                    pack_f16(acc[mi][ni][0], acc[mi][ni][1]);
                *(uint32_t*)&Chi[(size_t)(row + 8) * N + col] =
                    pack_f16(acc[mi][ni][2], acc[mi][ni][3]);
            }
        }
    }
}

// ---------------------------------------------------------------------------
// fp32 -> fp16 cast (elementwise, float4)
// ---------------------------------------------------------------------------
__global__ __launch_bounds__(256) void cast_kernel(
    const float* __restrict__ in, __half* __restrict__ hi, int n4)
{
    int i = blockIdx.x * blockDim.x + threadIdx.x;
    if (i >= n4) return;
    float4 v = ((const float4*)in)[i];
    ((uint2*)hi)[i] = make_uint2(pack_f16(v.x, v.y), pack_f16(v.z, v.w));
}

// ---------------------------------------------------------------------------
// fp32 [K][N] -> transposed fp16 [N][K]
// ---------------------------------------------------------------------------
__global__ __launch_bounds__(256) void castT_kernel(
    const float* __restrict__ w, __half* __restrict__ thi, int K, int N)
{
    __shared__ float t[32][33];
    const int n0 = blockIdx.x * 32, k0 = blockIdx.y * 32;
    const int tx = threadIdx.x & 31, ty = threadIdx.x >> 5;
    #pragma unroll
    for (int j = ty; j < 32; j += 8)
        t[j][tx] = w[(size_t)(k0 + j) * N + n0 + tx];
    __syncthreads();
    #pragma unroll
    for (int j = ty; j < 32; j += 8)
        thi[(size_t)(n0 + j) * K + k0 + tx] = __float2half_rn(t[tx][j]);
}

// ---------------------------------------------------------------------------
// HMMA flash attention, fp16 (unchanged from Round 11 — known-good).
// S = Qh Kh^T (1-pass); O += (Ph + Pl) Vh. Output: fp16 hi only.
// ---------------------------------------------------------------------------
#define AT_Q    0
#define AT_ST   16384
#define AT_STB  16384
#define AT_KH   0
#define AT_VH   8192
#define AT_SMEM (AT_ST + 2 * AT_STB)   // 49152

__global__ __launch_bounds__(256, 2) void attn_mma(
    const __half* __restrict__ qh, __half* __restrict__ ohi)
{
    extern __shared__ char sm[];
    const uint32_t sb = smem_u32(sm);
    const int tid  = threadIdx.x;
    const int lane = tid & 31;
    const int warp = tid >> 5;
    const int sub = lane >> 3, rin = lane & 7;
    const int g = lane >> 2, t = lane & 3;

    const int qt = blockIdx.x, head = blockIdx.y, batch = blockIdx.z;
    const size_t tok0 = (size_t)batch * SEQ;
    const size_t qbase = (tok0 + qt * 128) * QKVDIM + head * HDIM;

    #pragma unroll
    for (int j = 0; j < 4; j++) {
        int id = tid + j * 256;
        int r = id >> 3, c = id & 7;
        uint32_t sw = r * 128 + ((c ^ (r & 7)) << 4);
        cp_async16(sb + AT_Q + sw, (const char*)(qh + qbase) + (size_t)r * QKVDIM * 2 + c * 16);
    }
    CP_COMMIT();

    auto load_kv = [&](int s, int jt) {
        size_t kb = (tok0 + jt * 64) * QKVDIM + DIM + head * HDIM;
        size_t vb = kb + DIM;
        uint32_t st = sb + AT_ST + s * AT_STB;
        #pragma unroll
        for (int j = 0; j < 2; j++) {
            int id = tid + j * 256;
            int r = id >> 3, c = id & 7;
            uint32_t sw = r * 128 + ((c ^ (r & 7)) << 4);
            size_t go = (size_t)r * QKVDIM * 2 + c * 16;
            cp_async16(st + AT_KH + sw, (const char*)(qh + kb) + go);
            cp_async16(st + AT_VH + sw, (const char*)(qh + vb) + go);
        }
        CP_COMMIT();
    };

    load_kv(0, 0);
    load_kv(1, 1);

    CP_WAIT2();
    __syncthreads();
    uint32_t Qh[4][4];
    {
        int row = warp * 16 + (sub & 1) * 8 + rin;
        #pragma unroll
        for (int s4 = 0; s4 < 4; s4++) {
            int ch = 2 * s4 + (sub >> 1);
            uint32_t off = row * 128 + ((ch ^ (row & 7)) << 4);
            ldsm_x4(Qh[s4], sb + AT_Q + off);
        }
    }

    float m0 = -1e30f, m1 = -1e30f, l0 = 0.f, l1 = 0.f;
    float O[8][4];
    #pragma unroll
    for (int b = 0; b < 8; b++)
        #pragma unroll
        for (int q = 0; q < 4; q++) O[b][q] = 0.f;

    for (int jt = 0; jt < SEQ / 64; jt++) {
        const int s = jt & 1;
        if (jt == SEQ / 64 - 1) { CP_WAIT0(); } else { CP_WAIT1(); }
        __syncthreads();
        const uint32_t stb = sb + AT_ST + s * AT_STB;

        float S[8][4];
        #pragma unroll
        for (int b = 0; b < 8; b++)
            #pragma unroll
            for (int q = 0; q < 4; q++) S[b][q] = 0.f;

        #pragma unroll
        for (int s4 = 0; s4 < 4; s4++) {
            int bch = 2 * s4 + (sub & 1);
            #pragma unroll
            for (int jp = 0; jp < 4; jp++) {
                int row = jp * 16 + (sub >> 1) * 8 + rin;
                uint32_t off = row * 128 + ((bch ^ (row & 7)) << 4);
                uint32_t kh[4];
                ldsm_x4(kh, stb + AT_KH + off);
                mma_f16(S[2*jp],   Qh[s4], kh);
                mma_f16(S[2*jp+1], Qh[s4], kh + 2);
            }
        }

        float mx0 = -1e30f, mx1 = -1e30f;
        #pragma unroll
        for (int b = 0; b < 8; b++) {
            #pragma unroll
            for (int q = 0; q < 4; q++) S[b][q] *= SCALE;
            mx0 = fmaxf(mx0, fmaxf(S[b][0], S[b][1]));
            mx1 = fmaxf(mx1, fmaxf(S[b][2], S[b][3]));
        }
        #pragma unroll
        for (int off = 1; off < 4; off <<= 1) {
            mx0 = fmaxf(mx0, __shfl_xor_sync(0xffffffffu, mx0, off));
            mx1 = fmaxf(mx1, __shfl_xor_sync(0xffffffffu, mx1, off));
        }
        float mn0 = fmaxf(m0, mx0), mn1 = fmaxf(m1, mx1);
        float al0 = __expf(m0 - mn0), al1 = __expf(m1 - mn1);
        m0 = mn0; m1 = mn1;

        float rs0 = 0.f, rs1 = 0.f;
        #pragma unroll
        for (int b = 0; b < 8; b++) {
            S[b][0] = __expf(S[b][0] - mn0); rs0 += S[b][0];
            S[b][1] = __expf(S[b][1] - mn0); rs0 += S[b][1];
            S[b][2] = __expf(S[b][2] - mn1); rs1 += S[b][2];
            S[b][3] = __expf(S[b][3] - mn1); rs1 += S[b][3];
        }
        #pragma unroll
        for (int off = 1; off < 4; off <<= 1) {
            rs0 += __shfl_xor_sync(0xffffffffu, rs0, off);
            rs1 += __shfl_xor_sync(0xffffffffu, rs1, off);
        }
        l0 = l0 * al0 + rs0;
        l1 = l1 * al1 + rs1;
        #pragma unroll
        for (int b = 0; b < 8; b++) {
            O[b][0] *= al0; O[b][1] *= al0;
            O[b][2] *= al1; O[b][3] *= al1;
        }

        #pragma unroll
        for (int a = 0; a < 4; a++) {
            uint32_t Ph[4], Pl[4];
            Ph[0] = pack_f16(S[2*a][0],   S[2*a][1]);
            Ph[1] = pack_f16(S[2*a][2],   S[2*a][3]);
            Ph[2] = pack_f16(S[2*a+1][0], S[2*a+1][1]);
            Ph[3] = pack_f16(S[2*a+1][2], S[2*a+1][3]);
            Pl[0] = resid_f16(Ph[0], S[2*a][0],   S[2*a][1]);
            Pl[1] = resid_f16(Ph[1], S[2*a][2],   S[2*a][3]);
            Pl[2] = resid_f16(Ph[2], S[2*a+1][0], S[2*a+1][1]);
            Pl[3] = resid_f16(Ph[3], S[2*a+1][2], S[2*a+1][3]);

            int vrow = a * 16 + (sub & 1) * 8 + rin;
            #pragma unroll
            for (int bp = 0; bp < 4; bp++) {
                int ch = 2 * bp + (sub >> 1);
                uint32_t off = vrow * 128 + ((ch ^ (vrow & 7)) << 4);
                uint32_t vh[4];
                ldsm_x4_t(vh, stb + AT_VH + off);
                mma_f16(O[2*bp],   Ph, vh);
                mma_f16(O[2*bp],   Pl, vh);
                mma_f16(O[2*bp+1], Ph, vh + 2);
                mma_f16(O[2*bp+1], Pl, vh + 2);
            }
        }
        __syncthreads();
        if (jt + 2 < SEQ / 64) load_kv(s, jt + 2);
    }

    // epilogue: fp16 hi only
    float inv0 = 1.f / l0, inv1 = 1.f / l1;
    size_t t0 = tok0 + qt * 128 + warp * 16 + g;
    size_t t1 = t0 + 8;
    #pragma unroll
    for (int b = 0; b < 8; b++) {
        int col = head * HDIM + b * 8 + 2 * t;
        *(uint32_t*)&ohi[t0 * DIM + col] = pack_f16(O[b][0] * inv0, O[b][1] * inv0);
        *(uint32_t*)&ohi[t1 * DIM + col] = pack_f16(O[b][2] * inv1, O[b][3] * inv1);
    }
}

// ----------------------------------------------------------------------------
// Launch
// ----------------------------------------------------------------------------
extern "C" void kernel_launch(void* const* d_in, const int* in_sizes, int n_in,
                              void* d_out, int out_size)
{
    const float* x     = (const float*)d_in[0];
    const float* w_qkv = (const float*)d_in[1];
    const float* w_out = (const float*)d_in[2];
    const float* b_out = (const float*)d_in[3];
    float* out = (float*)d_out;

    void *p_xhi, *p_w1hi, *p_w2hi, *p_qh, *p_ahi;
    cudaGetSymbolAddress(&p_xhi, g_xhi);
    cudaGetSymbolAddress(&p_w1hi, g_w1hi);
    cudaGetSymbolAddress(&p_w2hi, g_w2hi);
    cudaGetSymbolAddress(&p_qh, g_qkvhi);
    cudaGetSymbolAddress(&p_ahi, g_ahi);

    cudaFuncSetAttribute(gemm_mma<0>, cudaFuncAttributeMaxDynamicSharedMemorySize, GEMM_SMEM);
    cudaFuncSetAttribute(gemm_mma<2>, cudaFuncAttributeMaxDynamicSharedMemorySize, GEMM_SMEM);
    cudaFuncSetAttribute(attn_mma,    cudaFuncAttributeMaxDynamicSharedMemorySize, AT_SMEM);

    // 0) casts: x -> fp16; w_qkv^T -> fp16; w_out^T -> fp16
    cast_kernel<<<(TOKENS * DIM / 4 + 255) / 256, 256>>>(
        x, (__half*)p_xhi, TOKENS * DIM / 4);
    castT_kernel<<<dim3(QKVDIM / 32, DIM / 32), 256>>>(
        w_qkv, (__half*)p_w1hi, DIM, QKVDIM);
    castT_kernel<<<dim3(DIM / 32, DIM / 32), 256>>>(
        w_out, (__half*)p_w2hi, DIM, DIM);

    // 1) qkv = x @ w_qkv -> fp16 (pure 1-pass)              [8192, 3072]
    gemm_mma<2><<<dim3(QKVDIM / 128, TOKENS / 128), 256, GEMM_SMEM>>>(
        (const __half*)p_xhi, (const __half*)p_w1hi,
        nullptr, nullptr, (__half*)p_qh, QKVDIM);

    // 2) attention -> fp16 (P-split retained)                [8192, 1024]
    attn_mma<<<dim3(SEQ / 128, HEADS, BATCH), 256, AT_SMEM>>>(
        (const __half*)p_qh, (__half*)p_ahi);

    // 3) out = attn @ w_out + b (pure 1-pass)                [8192, 1024]
    gemm_mma<0><<<dim3(DIM / 128, TOKENS / 128), 256, GEMM_SMEM>>>(
        (const __half*)p_ahi, (const __half*)p_w2hi,
        b_out, out, nullptr, DIM);
}

// round 13
// speedup vs baseline: 2.9293x; 1.2177x over previous
#include <cuda_runtime.h>
#include <cuda_fp16.h>
#include <cstdint>

// Problem constants
#define BATCH  8
#define SEQ    1024
#define DIM    1024
#define HEADS  16
#define HDIM   64
#define TOKENS (BATCH * SEQ)          // 8192
#define QKVDIM (3 * DIM)              // 3072
#define SCALE  0.03125f               // 1024^-0.5

// ---------------------------------------------------------------------------
// Scratch (device globals: allocation-guard safe)
// ---------------------------------------------------------------------------
__device__ __half g_xhi[(size_t)TOKENS * DIM];
__device__ __half g_w1hi[(size_t)QKVDIM * DIM];      // w_qkv^T [3072][1024]
__device__ __half g_w2hi[(size_t)DIM * DIM];         // w_out^T [1024][1024]
__device__ __half g_qkvhi[(size_t)TOKENS * QKVDIM];  // qkv [8192][3072]
__device__ __half g_ahi[(size_t)TOKENS * DIM];

// ---------------------------------------------------------------------------
// Helpers
// ---------------------------------------------------------------------------
__device__ __forceinline__ uint32_t smem_u32(const void* p) {
    uint32_t a;
    asm("{ .reg .u64 t; cvta.to.shared.u64 t, %1; cvt.u32.u64 %0, t; }" : "=r"(a) : "l"(p));
    return a;
}

__device__ __forceinline__ void cp_async16(uint32_t dst, const void* src) {
    asm volatile("cp.async.cg.shared.global [%0], [%1], 16;\n" :: "r"(dst), "l"(src));
}
#define CP_COMMIT() asm volatile("cp.async.commit_group;\n" ::: "memory")
#define CP_WAIT2()  asm volatile("cp.async.wait_group 2;\n" ::: "memory")
#define CP_WAIT1()  asm volatile("cp.async.wait_group 1;\n" ::: "memory")
#define CP_WAIT0()  asm volatile("cp.async.wait_group 0;\n" ::: "memory")

__device__ __forceinline__ void ldsm_x4(uint32_t* r, uint32_t addr) {
    asm volatile("ldmatrix.sync.aligned.m8n8.x4.shared.b16 {%0,%1,%2,%3}, [%4];"
                 : "=r"(r[0]), "=r"(r[1]), "=r"(r[2]), "=r"(r[3]) : "r"(addr));
}

__device__ __forceinline__ void ldsm_x4_t(uint32_t* r, uint32_t addr) {
    asm volatile("ldmatrix.sync.aligned.m8n8.x4.trans.shared.b16 {%0,%1,%2,%3}, [%4];"
                 : "=r"(r[0]), "=r"(r[1]), "=r"(r[2]), "=r"(r[3]) : "r"(addr));
}

// fp16 HMMA, fp32 accumulate
__device__ __forceinline__ void mma_f16(float* d, const uint32_t* a, const uint32_t* b) {
    asm volatile("mma.sync.aligned.m16n8k16.row.col.f32.f16.f16.f32 "
                 "{%0,%1,%2,%3}, {%4,%5,%6,%7}, {%8,%9}, {%0,%1,%2,%3};"
                 : "+f"(d[0]), "+f"(d[1]), "+f"(d[2]), "+f"(d[3])
                 : "r"(a[0]), "r"(a[1]), "r"(a[2]), "r"(a[3]), "r"(b[0]), "r"(b[1]));
}

// pack two fp32 into f16x2 (lo -> low half)
__device__ __forceinline__ uint32_t pack_f16(float lo, float hi) {
    uint32_t d;
    asm("cvt.rn.f16x2.f32 %0, %1, %2;" : "=r"(d) : "f"(hi), "f"(lo));
    return d;
}

// ---------------------------------------------------------------------------
// Pure fp16 HMMA GEMM (1-pass): C = A[M,K] @ W[N,K]^T
// OUT==0: write fp32 C (+bias).  OUT==2: fp16.
// Block 128x128, BK=64, 256 threads, 3-stage cp.async pipeline,
// XOR-swizzled smem (8 x 16B chunks per 128B row).
// ---------------------------------------------------------------------------
#define GK     1024
#define BK     64
#define NITER  (GK / BK)               // 16
#define TILEB  (128 * 128)             // 16 KB: [128 rows][64 f16 = 128B]
#define STAGEB (2 * TILEB)             // 32 KB (A, W)
#define NSTAGE 3
#define GEMM_SMEM (NSTAGE * STAGEB)    // 96 KB

template<int OUT>
__global__ __launch_bounds__(256, 2) void gemm_mma(
    const __half* __restrict__ Ahi,
    const __half* __restrict__ Whi,
    const float* __restrict__ bias, float* __restrict__ C,
    __half* __restrict__ Chi, int N)
{
    extern __shared__ char sm[];
    const uint32_t sbase = smem_u32(sm);
    const int tid  = threadIdx.x;
    const int lane = tid & 31;
    const int warp = tid >> 5;
    const int wm = warp & 1;
    const int wn = warp >> 1;
    const int m0 = blockIdx.y * 128;
    const int n0 = blockIdx.x * 128;

    float acc[4][4][4];
    #pragma unroll
    for (int i = 0; i < 4; i++)
        #pragma unroll
        for (int j = 0; j < 4; j++)
            #pragma unroll
            for (int q = 0; q < 4; q++) acc[i][j][q] = 0.f;

    auto soff = [&](int s, int t) -> uint32_t { return sbase + s * STAGEB + t * TILEB; };

    auto load_stage = [&](int s, int k0) {
        const __half* gsrc[2] = {Ahi + (size_t)m0 * GK + k0,
                                 Whi + (size_t)n0 * GK + k0};
        #pragma unroll
        for (int t = 0; t < 2; t++) {
            const char* gp = (const char*)gsrc[t];
            #pragma unroll
            for (int j = 0; j < 4; j++) {
                int id = tid + j * 256;           // 0..1023
                int r = id >> 3, c = id & 7;
                uint32_t sw = r * 128 + ((c ^ (r & 7)) << 4);
                cp_async16(soff(s, t) + sw, gp + (size_t)r * (GK * 2) + c * 16);
            }
        }
        CP_COMMIT();
    };

    load_stage(0, 0);
    load_stage(1, BK);

    const int sub = lane >> 3, rin = lane & 7;
    const int a_row_off = (sub & 1) * 8 + rin;
    const int a_chunk   = sub >> 1;
    const int b_row_off = (sub >> 1) * 8 + rin;
    const int b_chunk   = sub & 1;

    for (int it = 0; it < NITER; it++) {
        const int s = it % NSTAGE;
        if (it == NITER - 1) { CP_WAIT0(); } else { CP_WAIT1(); }
        __syncthreads();

        const uint32_t aH = soff(s, 0), wH = soff(s, 1);

        #pragma unroll
        for (int ks = 0; ks < 4; ks++) {          // 4 k16 steps per BK=64
            uint32_t Ah[4][4], Bh[4][2];

            #pragma unroll
            for (int mi = 0; mi < 4; mi++) {
                int row = wm * 64 + mi * 16 + a_row_off;
                int ch = ks * 2 + a_chunk;
                uint32_t off = row * 128 + ((ch ^ (row & 7)) << 4);
                ldsm_x4(Ah[mi], aH + off);
            }
            #pragma unroll
            for (int p = 0; p < 2; p++) {
                int row = wn * 32 + p * 16 + b_row_off;
                int ch = ks * 2 + b_chunk;
                uint32_t off = row * 128 + ((ch ^ (row & 7)) << 4);
                uint32_t t0[4];
                ldsm_x4(t0, wH + off);
                Bh[p*2  ][0] = t0[0]; Bh[p*2  ][1] = t0[1];
                Bh[p*2+1][0] = t0[2]; Bh[p*2+1][1] = t0[3];
            }

            #pragma unroll
            for (int mi = 0; mi < 4; mi++)
                #pragma unroll
                for (int ni = 0; ni < 4; ni++)
                    mma_f16(acc[mi][ni], Ah[mi], Bh[ni]);
        }
        if (it + 2 < NITER) load_stage((it + 2) % NSTAGE, (it + 2) * BK);
    }

    const int g = lane >> 2, c2 = (lane & 3) * 2;
    #pragma unroll
    for (int mi = 0; mi < 4; mi++) {
        int row = m0 + wm * 64 + mi * 16 + g;
        #pragma unroll
        for (int ni = 0; ni < 4; ni++) {
            int col = n0 + wn * 32 + ni * 8 + c2;
            if (OUT == 0) {
                float b0 = 0.f, b1 = 0.f;
                if (bias) { b0 = bias[col]; b1 = bias[col + 1]; }
                float2 v0 = make_float2(acc[mi][ni][0] + b0, acc[mi][ni][1] + b1);
                float2 v1 = make_float2(acc[mi][ni][2] + b0, acc[mi][ni][3] + b1);
                *(float2*)&C[(size_t)row * N + col] = v0;
                *(float2*)&C[(size_t)(row + 8) * N + col] = v1;
            } else {
                *(uint32_t*)&Chi[(size_t)row * N + col] =
                    pack_f16(acc[mi][ni][0], acc[mi][ni][1]);
                *(uint32_t*)&Chi[(size_t)(row + 8) * N + col] =
                    pack_f16(acc[mi][ni][2], acc[mi][ni][3]);
            }
        }
    }
}

// ---------------------------------------------------------------------------
// fp32 -> fp16 cast (elementwise, float4)
// ---------------------------------------------------------------------------
__global__ __launch_bounds__(256) void cast_kernel(
    const float* __restrict__ in, __half* __restrict__ hi, int n4)
{
    int i = blockIdx.x * blockDim.x + threadIdx.x;
    if (i >= n4) return;
    float4 v = ((const float4*)in)[i];
    ((uint2*)hi)[i] = make_uint2(pack_f16(v.x, v.y), pack_f16(v.z, v.w));
}

// ---------------------------------------------------------------------------
// fp32 [K][N] -> transposed fp16 [N][K]
// ---------------------------------------------------------------------------
__global__ __launch_bounds__(256) void castT_kernel(
    const float* __restrict__ w, __half* __restrict__ thi, int K, int N)
{
    __shared__ float t[32][33];
    const int n0 = blockIdx.x * 32, k0 = blockIdx.y * 32;
    const int tx = threadIdx.x & 31, ty = threadIdx.x >> 5;
    #pragma unroll
    for (int j = ty; j < 32; j += 8)
        t[j][tx] = w[(size_t)(k0 + j) * N + n0 + tx];
    __syncthreads();
    #pragma unroll
    for (int j = ty; j < 32; j += 8)
        thi[(size_t)(n0 + j) * K + k0 + tx] = __float2half_rn(t[tx][j]);
}

// ---------------------------------------------------------------------------
// HMMA flash attention, pure fp16 (S = Qh Kh^T; O += Ph Vh — no splits).
// 2 CTAs/SM, 48 KB smem each.
// ---------------------------------------------------------------------------
#define AT_Q    0
#define AT_ST   16384
#define AT_STB  16384
#define AT_KH   0
#define AT_VH   8192
#define AT_SMEM (AT_ST + 2 * AT_STB)   // 49152

__global__ __launch_bounds__(256, 2) void attn_mma(
    const __half* __restrict__ qh, __half* __restrict__ ohi)
{
    extern __shared__ char sm[];
    const uint32_t sb = smem_u32(sm);
    const int tid  = threadIdx.x;
    const int lane = tid & 31;
    const int warp = tid >> 5;
    const int sub = lane >> 3, rin = lane & 7;
    const int g = lane >> 2, t = lane & 3;

    const int qt = blockIdx.x, head = blockIdx.y, batch = blockIdx.z;
    const size_t tok0 = (size_t)batch * SEQ;
    const size_t qbase = (tok0 + qt * 128) * QKVDIM + head * HDIM;

    #pragma unroll
    for (int j = 0; j < 4; j++) {
        int id = tid + j * 256;
        int r = id >> 3, c = id & 7;
        uint32_t sw = r * 128 + ((c ^ (r & 7)) << 4);
        cp_async16(sb + AT_Q + sw, (const char*)(qh + qbase) + (size_t)r * QKVDIM * 2 + c * 16);
    }
    CP_COMMIT();

    auto load_kv = [&](int s, int jt) {
        size_t kb = (tok0 + jt * 64) * QKVDIM + DIM + head * HDIM;
        size_t vb = kb + DIM;
        uint32_t st = sb + AT_ST + s * AT_STB;
        #pragma unroll
        for (int j = 0; j < 2; j++) {
            int id = tid + j * 256;
            int r = id >> 3, c = id & 7;
            uint32_t sw = r * 128 + ((c ^ (r & 7)) << 4);
            size_t go = (size_t)r * QKVDIM * 2 + c * 16;
            cp_async16(st + AT_KH + sw, (const char*)(qh + kb) + go);
            cp_async16(st + AT_VH + sw, (const char*)(qh + vb) + go);
        }
        CP_COMMIT();
    };

    load_kv(0, 0);
    load_kv(1, 1);

    CP_WAIT2();
    __syncthreads();
    uint32_t Qh[4][4];
    {
        int row = warp * 16 + (sub & 1) * 8 + rin;
        #pragma unroll
        for (int s4 = 0; s4 < 4; s4++) {
            int ch = 2 * s4 + (sub >> 1);
            uint32_t off = row * 128 + ((ch ^ (row & 7)) << 4);
            ldsm_x4(Qh[s4], sb + AT_Q + off);
        }
    }

    float m0 = -1e30f, m1 = -1e30f, l0 = 0.f, l1 = 0.f;
    float O[8][4];
    #pragma unroll
    for (int b = 0; b < 8; b++)
        #pragma unroll
        for (int q = 0; q < 4; q++) O[b][q] = 0.f;

    for (int jt = 0; jt < SEQ / 64; jt++) {
        const int s = jt & 1;
        if (jt == SEQ / 64 - 1) { CP_WAIT0(); } else { CP_WAIT1(); }
        __syncthreads();
        const uint32_t stb = sb + AT_ST + s * AT_STB;

        float S[8][4];
        #pragma unroll
        for (int b = 0; b < 8; b++)
            #pragma unroll
            for (int q = 0; q < 4; q++) S[b][q] = 0.f;

        #pragma unroll
        for (int s4 = 0; s4 < 4; s4++) {
            int bch = 2 * s4 + (sub & 1);
            #pragma unroll
            for (int jp = 0; jp < 4; jp++) {
                int row = jp * 16 + (sub >> 1) * 8 + rin;
                uint32_t off = row * 128 + ((bch ^ (row & 7)) << 4);
                uint32_t kh[4];
                ldsm_x4(kh, stb + AT_KH + off);
                mma_f16(S[2*jp],   Qh[s4], kh);
                mma_f16(S[2*jp+1], Qh[s4], kh + 2);
            }
        }

        float mx0 = -1e30f, mx1 = -1e30f;
        #pragma unroll
        for (int b = 0; b < 8; b++) {
            #pragma unroll
            for (int q = 0; q < 4; q++) S[b][q] *= SCALE;
            mx0 = fmaxf(mx0, fmaxf(S[b][0], S[b][1]));
            mx1 = fmaxf(mx1, fmaxf(S[b][2], S[b][3]));
        }
        #pragma unroll
        for (int off = 1; off < 4; off <<= 1) {
            mx0 = fmaxf(mx0, __shfl_xor_sync(0xffffffffu, mx0, off));
            mx1 = fmaxf(mx1, __shfl_xor_sync(0xffffffffu, mx1, off));
        }
        float mn0 = fmaxf(m0, mx0), mn1 = fmaxf(m1, mx1);
        float al0 = __expf(m0 - mn0), al1 = __expf(m1 - mn1);
        m0 = mn0; m1 = mn1;

        float rs0 = 0.f, rs1 = 0.f;
        #pragma unroll
        for (int b = 0; b < 8; b++) {
            S[b][0] = __expf(S[b][0] - mn0); rs0 += S[b][0];
            S[b][1] = __expf(S[b][1] - mn0); rs0 += S[b][1];
            S[b][2] = __expf(S[b][2] - mn1); rs1 += S[b][2];
            S[b][3] = __expf(S[b][3] - mn1); rs1 += S[b][3];
        }
        #pragma unroll
        for (int off = 1; off < 4; off <<= 1) {
            rs0 += __shfl_xor_sync(0xffffffffu, rs0, off);
            rs1 += __shfl_xor_sync(0xffffffffu, rs1, off);
        }
        l0 = l0 * al0 + rs0;
        l1 = l1 * al1 + rs1;
        #pragma unroll
        for (int b = 0; b < 8; b++) {
            O[b][0] *= al0; O[b][1] *= al0;
            O[b][2] *= al1; O[b][3] *= al1;
        }

        // O += Ph Vh (1-pass)
        #pragma unroll
        for (int a = 0; a < 4; a++) {
            uint32_t Ph[4];
            Ph[0] = pack_f16(S[2*a][0],   S[2*a][1]);
            Ph[1] = pack_f16(S[2*a][2],   S[2*a][3]);
            Ph[2] = pack_f16(S[2*a+1][0], S[2*a+1][1]);
            Ph[3] = pack_f16(S[2*a+1][2], S[2*a+1][3]);

            int vrow = a * 16 + (sub & 1) * 8 + rin;
            #pragma unroll
            for (int bp = 0; bp < 4; bp++) {
                int ch = 2 * bp + (sub >> 1);
                uint32_t off = vrow * 128 + ((ch ^ (vrow & 7)) << 4);
                uint32_t vh[4];
                ldsm_x4_t(vh, stb + AT_VH + off);
                mma_f16(O[2*bp],   Ph, vh);
                mma_f16(O[2*bp+1], Ph, vh + 2);
            }
        }
        __syncthreads();
        if (jt + 2 < SEQ / 64) load_kv(s, jt + 2);
    }

    float inv0 = 1.f / l0, inv1 = 1.f / l1;
    size_t t0 = tok0 + qt * 128 + warp * 16 + g;
    size_t t1 = t0 + 8;
    #pragma unroll
    for (int b = 0; b < 8; b++) {
        int col = head * HDIM + b * 8 + 2 * t;
        *(uint32_t*)&ohi[t0 * DIM + col] = pack_f16(O[b][0] * inv0, O[b][1] * inv0);
        *(uint32_t*)&ohi[t1 * DIM + col] = pack_f16(O[b][2] * inv1, O[b][3] * inv1);
    }
}

// ----------------------------------------------------------------------------
// Launch
// ----------------------------------------------------------------------------
extern "C" void kernel_launch(void* const* d_in, const int* in_sizes, int n_in,
                              void* d_out, int out_size)
{
    const float* x     = (const float*)d_in[0];
    const float* w_qkv = (const float*)d_in[1];
    const float* w_out = (const float*)d_in[2];
    const float* b_out = (const float*)d_in[3];
    float* out = (float*)d_out;

    void *p_xhi, *p_w1hi, *p_w2hi, *p_qh, *p_ahi;
    cudaGetSymbolAddress(&p_xhi, g_xhi);
    cudaGetSymbolAddress(&p_w1hi, g_w1hi);
    cudaGetSymbolAddress(&p_w2hi, g_w2hi);
    cudaGetSymbolAddress(&p_qh, g_qkvhi);
    cudaGetSymbolAddress(&p_ahi, g_ahi);

    cudaFuncSetAttribute(gemm_mma<0>, cudaFuncAttributeMaxDynamicSharedMemorySize, GEMM_SMEM);
    cudaFuncSetAttribute(gemm_mma<2>, cudaFuncAttributeMaxDynamicSharedMemorySize, GEMM_SMEM);
    cudaFuncSetAttribute(attn_mma,    cudaFuncAttributeMaxDynamicSharedMemorySize, AT_SMEM);

    // 0) casts: x -> fp16; w_qkv^T -> fp16; w_out^T -> fp16
    cast_kernel<<<(TOKENS * DIM / 4 + 255) / 256, 256>>>(
        x, (__half*)p_xhi, TOKENS * DIM / 4);
    castT_kernel<<<dim3(QKVDIM / 32, DIM / 32), 256>>>(
        w_qkv, (__half*)p_w1hi, DIM, QKVDIM);
    castT_kernel<<<dim3(DIM / 32, DIM / 32), 256>>>(
        w_out, (__half*)p_w2hi, DIM, DIM);

    // 1) qkv = x @ w_qkv -> fp16 (1-pass, BK=64)            [8192, 3072]
    gemm_mma<2><<<dim3(QKVDIM / 128, TOKENS / 128), 256, GEMM_SMEM>>>(
        (const __half*)p_xhi, (const __half*)p_w1hi,
        nullptr, nullptr, (__half*)p_qh, QKVDIM);

    // 2) attention -> fp16 (pure 1-pass)                     [8192, 1024]
    attn_mma<<<dim3(SEQ / 128, HEADS, BATCH), 256, AT_SMEM>>>(
        (const __half*)p_qh, (__half*)p_ahi);

    // 3) out = attn @ w_out + b (1-pass, BK=64)              [8192, 1024]
    gemm_mma<0><<<dim3(DIM / 128, TOKENS / 128), 256, GEMM_SMEM>>>(
        (const __half*)p_ahi, (const __half*)p_w2hi,
        b_out, out, nullptr, DIM);
}